// round 1
// baseline (speedup 1.0000x reference)
#include <cuda_runtime.h>
#include <cstdint>

#define N_NODES 50000
#define N_EDGES 600000
#define N_RELS  19
#define D_IN    128
#define D_HID   64
#define D_OUT   2

// Scratch (device globals — no allocation allowed in kernel_launch)
__device__ float g_T1[(size_t)N_NODES * N_RELS * D_HID];   // 243 MB
__device__ float g_h1[(size_t)N_NODES * D_HID];            // agg1 -> pre-relu h1
__device__ float g_T2[(size_t)N_NODES * N_RELS * D_OUT];   // 7.6 MB

// ---------------------------------------------------------------------------
// Kernel 1: per-relation transform T1 = feat @ W1[r]  (blockIdx.y < 19)
//           plus self-loop init     h1 = feat @ loop1 + b1 (blockIdx.y == 19)
// Block: 32 nodes x 1 relation, 256 threads.
// feat tile staged transposed in smem; W column read via LDG (L1-resident,
// 32KB per relation). Inner product uses packed fma.rn.f32x2 (2 nodes/op).
// ---------------------------------------------------------------------------
__global__ void __launch_bounds__(256) k_transform1(
    const float* __restrict__ feat, const float* __restrict__ W1,
    const float* __restrict__ loop1, const float* __restrict__ b1) {
  __shared__ __align__(16) float sFT[D_IN][36];   // [k][node], pad 36 (16B-aligned rows)
  const int r  = blockIdx.y;
  const int n0 = blockIdx.x * 32;

  // Stage feat[n0:n0+32][0:128] transposed, coalesced float4 reads.
  for (int i = threadIdx.x; i < 32 * 32; i += 256) {
    int n = i >> 5, kq = i & 31;
    float4 v = make_float4(0.f, 0.f, 0.f, 0.f);
    if (n0 + n < N_NODES)
      v = *(const float4*)(feat + (size_t)(n0 + n) * D_IN + kq * 4);
    sFT[kq * 4 + 0][n] = v.x;
    sFT[kq * 4 + 1][n] = v.y;
    sFT[kq * 4 + 2][n] = v.z;
    sFT[kq * 4 + 3][n] = v.w;
  }
  __syncthreads();

  const int o  = threadIdx.x & 63;   // output column
  const int ng = threadIdx.x >> 6;   // node group (8 nodes each)
  const float* __restrict__ wcol =
      ((r < N_RELS) ? (W1 + (size_t)r * D_IN * D_HID) : loop1) + o;

  unsigned long long a0 = 0, a1 = 0, a2 = 0, a3 = 0;  // 4 x f32x2 = 8 nodes
  #pragma unroll 4
  for (int k = 0; k < D_IN; k++) {
    float w = __ldg(wcol + k * D_HID);
    unsigned long long w2;
    asm("mov.b64 %0, {%1, %1};" : "=l"(w2) : "f"(w));
    const ulonglong2* fp = (const ulonglong2*)&sFT[k][ng * 8];
    ulonglong2 fA = fp[0];   // nodes 0..3 (packed pairs)
    ulonglong2 fB = fp[1];   // nodes 4..7
    asm("fma.rn.f32x2 %0, %1, %2, %0;" : "+l"(a0) : "l"(fA.x), "l"(w2));
    asm("fma.rn.f32x2 %0, %1, %2, %0;" : "+l"(a1) : "l"(fA.y), "l"(w2));
    asm("fma.rn.f32x2 %0, %1, %2, %0;" : "+l"(a2) : "l"(fB.x), "l"(w2));
    asm("fma.rn.f32x2 %0, %1, %2, %0;" : "+l"(a3) : "l"(fB.y), "l"(w2));
  }

  float v[8];
  asm("mov.b64 {%0,%1}, %2;" : "=f"(v[0]), "=f"(v[1]) : "l"(a0));
  asm("mov.b64 {%0,%1}, %2;" : "=f"(v[2]), "=f"(v[3]) : "l"(a1));
  asm("mov.b64 {%0,%1}, %2;" : "=f"(v[4]), "=f"(v[5]) : "l"(a2));
  asm("mov.b64 {%0,%1}, %2;" : "=f"(v[6]), "=f"(v[7]) : "l"(a3));

  if (r < N_RELS) {
    #pragma unroll
    for (int j = 0; j < 8; j++) {
      int n = n0 + ng * 8 + j;
      if (n < N_NODES)
        g_T1[((size_t)n * N_RELS + r) * D_HID + o] = v[j];
    }
  } else {
    float bias = __ldg(b1 + o);
    #pragma unroll
    for (int j = 0; j < 8; j++) {
      int n = n0 + ng * 8 + j;
      if (n < N_NODES)
        g_h1[(size_t)n * D_HID + o] = v[j] + bias;
    }
  }
}

// ---------------------------------------------------------------------------
// Kernel 2: edge gather + scatter-add (layer 1).
// 16 threads per edge; each does one float4 gather + one red.v4.f32.
// ---------------------------------------------------------------------------
__global__ void __launch_bounds__(256) k_edge1(
    const int* __restrict__ src, const int* __restrict__ dst,
    const int* __restrict__ et) {
  int idx = blockIdx.x * 256 + threadIdx.x;
  int e = idx >> 4;
  if (e >= N_EDGES) return;
  int q = idx & 15;
  int s = __ldg(src + e), d = __ldg(dst + e), r = __ldg(et + e);
  const float4 v =
      *(const float4*)(g_T1 + ((size_t)s * N_RELS + r) * D_HID + q * 4);
  float* p = g_h1 + (size_t)d * D_HID + q * 4;
  asm volatile("red.global.add.v4.f32 [%0], {%1,%2,%3,%4};"
               :: "l"(p), "f"(v.x), "f"(v.y), "f"(v.z), "f"(v.w)
               : "memory");
}

// ---------------------------------------------------------------------------
// Kernel 3: layer-2 transform (all 19 relations) + self-loop + bias.
// ReLU applied when staging h1 into smem. Writes T2 and initializes d_out
// with the self-loop term so k_edge2 only needs to reduce into it.
// Block: 64 nodes, 256 threads (4 rel-groups per node).
// ---------------------------------------------------------------------------
__global__ void __launch_bounds__(256) k_layer2(
    const float* __restrict__ W2, const float* __restrict__ loop2,
    const float* __restrict__ b2, float* __restrict__ out) {
  __shared__ float sH[64][65];          // relu(h1) tile
  __shared__ float sW[N_RELS * D_HID * D_OUT];  // 2432 floats
  __shared__ float sL[D_HID * D_OUT + D_OUT];   // loop2 + b2
  const int n0 = blockIdx.x * 64;

  for (int i = threadIdx.x; i < N_RELS * D_HID * D_OUT; i += 256)
    sW[i] = W2[i];
  for (int i = threadIdx.x; i < D_HID * D_OUT; i += 256)
    sL[i] = loop2[i];
  if (threadIdx.x < D_OUT) sL[D_HID * D_OUT + threadIdx.x] = b2[threadIdx.x];
  for (int i = threadIdx.x; i < 64 * D_HID; i += 256) {
    int n = i >> 6, k = i & 63;
    float v = 0.f;
    if (n0 + n < N_NODES) v = g_h1[(size_t)(n0 + n) * D_HID + k];
    sH[n][k] = fmaxf(v, 0.f);
  }
  __syncthreads();

  const int node = threadIdx.x >> 2;
  const int rg   = threadIdx.x & 3;
  float acc[5][2] = {};
  float s0 = 0.f, s1 = 0.f;
  for (int k = 0; k < D_HID; k++) {
    float f = sH[node][k];
    #pragma unroll
    for (int i = 0; i < 5; i++) {
      int r = rg + 4 * i;
      if (r < N_RELS) {
        acc[i][0] += f * sW[(r * D_HID + k) * 2];
        acc[i][1] += f * sW[(r * D_HID + k) * 2 + 1];
      }
    }
    if (rg == 0) { s0 += f * sL[k * 2]; s1 += f * sL[k * 2 + 1]; }
  }

  int n = n0 + node;
  if (n < N_NODES) {
    #pragma unroll
    for (int i = 0; i < 5; i++) {
      int r = rg + 4 * i;
      if (r < N_RELS)
        *(float2*)&g_T2[((size_t)n * N_RELS + r) * D_OUT] =
            make_float2(acc[i][0], acc[i][1]);
    }
    if (rg == 0)
      *(float2*)&out[(size_t)n * D_OUT] =
          make_float2(s0 + sL[D_HID * D_OUT], s1 + sL[D_HID * D_OUT + 1]);
  }
}

// ---------------------------------------------------------------------------
// Kernel 4: edge gather + scatter-add (layer 2). One thread per edge.
// ---------------------------------------------------------------------------
__global__ void __launch_bounds__(256) k_edge2(
    const int* __restrict__ src, const int* __restrict__ dst,
    const int* __restrict__ et, float* __restrict__ out) {
  int e = blockIdx.x * 256 + threadIdx.x;
  if (e >= N_EDGES) return;
  int s = __ldg(src + e), d = __ldg(dst + e), r = __ldg(et + e);
  const float2 v = *(const float2*)(g_T2 + ((size_t)s * N_RELS + r) * D_OUT);
  asm volatile("red.global.add.v2.f32 [%0], {%1,%2};"
               :: "l"(out + (size_t)d * D_OUT), "f"(v.x), "f"(v.y)
               : "memory");
}

// ---------------------------------------------------------------------------
extern "C" void kernel_launch(void* const* d_in, const int* in_sizes, int n_in,
                              void* d_out, int out_size) {
  const float* feat  = (const float*)d_in[0];
  const float* W1    = (const float*)d_in[1];
  const float* loop1 = (const float*)d_in[2];
  const float* b1    = (const float*)d_in[3];
  const float* W2    = (const float*)d_in[4];
  const float* loop2 = (const float*)d_in[5];
  const float* b2    = (const float*)d_in[6];
  const int*   src   = (const int*)d_in[7];
  const int*   dst   = (const int*)d_in[8];
  const int*   et    = (const int*)d_in[9];
  float* out = (float*)d_out;

  // Layer 1: transforms for 19 relations + self-loop init of g_h1 (y == 19)
  dim3 g1((N_NODES + 31) / 32, N_RELS + 1);
  k_transform1<<<g1, 256>>>(feat, W1, loop1, b1);

  // Layer 1: edge aggregation into g_h1
  k_edge1<<<(N_EDGES * 16 + 255) / 256, 256>>>(src, dst, et);

  // Layer 2: transform + self-loop (initializes d_out)
  k_layer2<<<(N_NODES + 63) / 64, 256>>>(W2, loop2, b2, out);

  // Layer 2: edge aggregation into d_out
  k_edge2<<<(N_EDGES + 255) / 256, 256>>>(src, dst, et, out);
}

// round 2
// speedup vs baseline: 1.8531x; 1.8531x over previous
#include <cuda_runtime.h>
#include <cstdint>

#define N_NODES 50000
#define N_EDGES 600000
#define N_RELS  19
#define D_IN    128
#define D_HID   64
#define D_OUT   2

// Scratch (device globals — no allocation allowed in kernel_launch)
__device__ float g_T1[(size_t)N_NODES * N_RELS * D_HID];   // 243 MB
__device__ float g_h1[(size_t)N_NODES * D_HID];            // agg1 -> pre-relu h1
__device__ float g_T2[(size_t)N_NODES * N_RELS * D_OUT];   // 7.6 MB

// ---------------------------------------------------------------------------
// Kernel 1 (v2): tiled GEMM. Block = 128 nodes x 64 outputs, one relation.
// blockIdx.y < 19: T1[n,r,:] = feat[n,:] @ W1[r]
// blockIdx.y == 19: h1[n,:]  = feat[n,:] @ loop1 + b1   (self-loop init)
// K staged in 32-chunks; feat tile + W chunk both in smem. Micro-tile:
// 8 nodes x 4 outputs per thread, output-pairs packed in fma.rn.f32x2.
// Inner loop: 2 LDS.128(w) + 8 LDS.64(f) + 20 mov + 32 FMA2 per 2 k-steps
// = 62 issues per 64-cycle FMA-pipe window -> FMA-bound.
// ---------------------------------------------------------------------------
__global__ void __launch_bounds__(256) k_transform1(
    const float* __restrict__ feat, const float* __restrict__ W1,
    const float* __restrict__ loop1, const float* __restrict__ b1) {
  __shared__ __align__(16) float sF[128][36];   // [node][k-chunk], pitch 144B
  __shared__ __align__(16) float sW[32][64];    // [k][output]
  const int r  = blockIdx.y;
  const int n0 = blockIdx.x * 128;
  const int ng = threadIdx.x >> 4;   // 0..15 -> nodes 8ng..8ng+7
  const int og = threadIdx.x & 15;   // 0..15 -> outputs 4og..4og+3
  const float* __restrict__ Wb =
      (r < N_RELS) ? W1 + (size_t)r * (D_IN * D_HID) : loop1;

  unsigned long long acc[8][2];
  #pragma unroll
  for (int j = 0; j < 8; j++) { acc[j][0] = 0ull; acc[j][1] = 0ull; }

  for (int k0 = 0; k0 < D_IN; k0 += 32) {
    __syncthreads();
    // Stage feat[n0:n0+128][k0:k0+32]  (coalesced float4 loads/stores)
    #pragma unroll
    for (int t = 0; t < 4; t++) {
      int i = threadIdx.x + t * 256;
      int n = i >> 3, c = i & 7;
      float4 v = make_float4(0.f, 0.f, 0.f, 0.f);
      if (n0 + n < N_NODES)
        v = *(const float4*)(feat + (size_t)(n0 + n) * D_IN + k0 + c * 4);
      *(float4*)&sF[n][c * 4] = v;
    }
    // Stage W chunk [32][64]
    #pragma unroll
    for (int t = 0; t < 2; t++) {
      int i = threadIdx.x + t * 256;
      int kk = i >> 4, c = i & 15;
      *(float4*)&sW[kk][c * 4] =
          *(const float4*)(Wb + (size_t)(k0 + kk) * D_HID + c * 4);
    }
    __syncthreads();

    #pragma unroll
    for (int kk = 0; kk < 32; kk += 2) {
      unsigned long long w0a, w0b, w1a, w1b;
      float4 wv0 = *(const float4*)&sW[kk][og * 4];
      float4 wv1 = *(const float4*)&sW[kk + 1][og * 4];
      asm("mov.b64 %0, {%1, %2};" : "=l"(w0a) : "f"(wv0.x), "f"(wv0.y));
      asm("mov.b64 %0, {%1, %2};" : "=l"(w0b) : "f"(wv0.z), "f"(wv0.w));
      asm("mov.b64 %0, {%1, %2};" : "=l"(w1a) : "f"(wv1.x), "f"(wv1.y));
      asm("mov.b64 %0, {%1, %2};" : "=l"(w1b) : "f"(wv1.z), "f"(wv1.w));
      #pragma unroll
      for (int j = 0; j < 8; j++) {
        float2 f = *(const float2*)&sF[ng * 8 + j][kk];
        unsigned long long s0, s1;
        asm("mov.b64 %0, {%1, %1};" : "=l"(s0) : "f"(f.x));
        asm("mov.b64 %0, {%1, %1};" : "=l"(s1) : "f"(f.y));
        asm("fma.rn.f32x2 %0, %1, %2, %0;" : "+l"(acc[j][0]) : "l"(s0), "l"(w0a));
        asm("fma.rn.f32x2 %0, %1, %2, %0;" : "+l"(acc[j][1]) : "l"(s0), "l"(w0b));
        asm("fma.rn.f32x2 %0, %1, %2, %0;" : "+l"(acc[j][0]) : "l"(s1), "l"(w1a));
        asm("fma.rn.f32x2 %0, %1, %2, %0;" : "+l"(acc[j][1]) : "l"(s1), "l"(w1b));
      }
    }
  }

  if (r < N_RELS) {
    #pragma unroll
    for (int j = 0; j < 8; j++) {
      int n = n0 + ng * 8 + j;
      if (n < N_NODES) {
        ulonglong2 v;
        v.x = acc[j][0];
        v.y = acc[j][1];
        *(ulonglong2*)(g_T1 + ((size_t)n * N_RELS + r) * D_HID + og * 4) = v;
      }
    }
  } else {
    float4 bv = *(const float4*)(b1 + og * 4);
    #pragma unroll
    for (int j = 0; j < 8; j++) {
      int n = n0 + ng * 8 + j;
      if (n < N_NODES) {
        float o0, o1, o2, o3;
        asm("mov.b64 {%0,%1}, %2;" : "=f"(o0), "=f"(o1) : "l"(acc[j][0]));
        asm("mov.b64 {%0,%1}, %2;" : "=f"(o2), "=f"(o3) : "l"(acc[j][1]));
        *(float4*)(g_h1 + (size_t)n * D_HID + og * 4) =
            make_float4(o0 + bv.x, o1 + bv.y, o2 + bv.z, o3 + bv.w);
      }
    }
  }
}

// ---------------------------------------------------------------------------
// Kernel 2: edge gather + scatter-add (layer 1).
// 16 threads per edge; each does one float4 gather + one red.v4.f32.
// ---------------------------------------------------------------------------
__global__ void __launch_bounds__(256) k_edge1(
    const int* __restrict__ src, const int* __restrict__ dst,
    const int* __restrict__ et) {
  int idx = blockIdx.x * 256 + threadIdx.x;
  int e = idx >> 4;
  if (e >= N_EDGES) return;
  int q = idx & 15;
  int s = __ldg(src + e), d = __ldg(dst + e), r = __ldg(et + e);
  const float4 v =
      *(const float4*)(g_T1 + ((size_t)s * N_RELS + r) * D_HID + q * 4);
  float* p = g_h1 + (size_t)d * D_HID + q * 4;
  asm volatile("red.global.add.v4.f32 [%0], {%1,%2,%3,%4};"
               :: "l"(p), "f"(v.x), "f"(v.y), "f"(v.z), "f"(v.w)
               : "memory");
}

// ---------------------------------------------------------------------------
// Kernel 3: layer-2 transform (all 19 relations) + self-loop + bias.
// ReLU applied when staging h1 into smem. Writes T2 and initializes d_out
// with the self-loop term so k_edge2 only needs to reduce into it.
// ---------------------------------------------------------------------------
__global__ void __launch_bounds__(256) k_layer2(
    const float* __restrict__ W2, const float* __restrict__ loop2,
    const float* __restrict__ b2, float* __restrict__ out) {
  __shared__ float sH[64][65];
  __shared__ float sW[N_RELS * D_HID * D_OUT];
  __shared__ float sL[D_HID * D_OUT + D_OUT];
  const int n0 = blockIdx.x * 64;

  for (int i = threadIdx.x; i < N_RELS * D_HID * D_OUT; i += 256)
    sW[i] = W2[i];
  for (int i = threadIdx.x; i < D_HID * D_OUT; i += 256)
    sL[i] = loop2[i];
  if (threadIdx.x < D_OUT) sL[D_HID * D_OUT + threadIdx.x] = b2[threadIdx.x];
  for (int i = threadIdx.x; i < 64 * D_HID; i += 256) {
    int n = i >> 6, k = i & 63;
    float v = 0.f;
    if (n0 + n < N_NODES) v = g_h1[(size_t)(n0 + n) * D_HID + k];
    sH[n][k] = fmaxf(v, 0.f);
  }
  __syncthreads();

  const int node = threadIdx.x >> 2;
  const int rg   = threadIdx.x & 3;
  float acc[5][2] = {};
  float s0 = 0.f, s1 = 0.f;
  for (int k = 0; k < D_HID; k++) {
    float f = sH[node][k];
    #pragma unroll
    for (int i = 0; i < 5; i++) {
      int r = rg + 4 * i;
      if (r < N_RELS) {
        acc[i][0] += f * sW[(r * D_HID + k) * 2];
        acc[i][1] += f * sW[(r * D_HID + k) * 2 + 1];
      }
    }
    if (rg == 0) { s0 += f * sL[k * 2]; s1 += f * sL[k * 2 + 1]; }
  }

  int n = n0 + node;
  if (n < N_NODES) {
    #pragma unroll
    for (int i = 0; i < 5; i++) {
      int r = rg + 4 * i;
      if (r < N_RELS)
        *(float2*)&g_T2[((size_t)n * N_RELS + r) * D_OUT] =
            make_float2(acc[i][0], acc[i][1]);
    }
    if (rg == 0)
      *(float2*)&out[(size_t)n * D_OUT] =
          make_float2(s0 + sL[D_HID * D_OUT], s1 + sL[D_HID * D_OUT + 1]);
  }
}

// ---------------------------------------------------------------------------
// Kernel 4: edge gather + scatter-add (layer 2). One thread per edge.
// ---------------------------------------------------------------------------
__global__ void __launch_bounds__(256) k_edge2(
    const int* __restrict__ src, const int* __restrict__ dst,
    const int* __restrict__ et, float* __restrict__ out) {
  int e = blockIdx.x * 256 + threadIdx.x;
  if (e >= N_EDGES) return;
  int s = __ldg(src + e), d = __ldg(dst + e), r = __ldg(et + e);
  const float2 v = *(const float2*)(g_T2 + ((size_t)s * N_RELS + r) * D_OUT);
  asm volatile("red.global.add.v2.f32 [%0], {%1,%2};"
               :: "l"(out + (size_t)d * D_OUT), "f"(v.x), "f"(v.y)
               : "memory");
}

// ---------------------------------------------------------------------------
extern "C" void kernel_launch(void* const* d_in, const int* in_sizes, int n_in,
                              void* d_out, int out_size) {
  const float* feat  = (const float*)d_in[0];
  const float* W1    = (const float*)d_in[1];
  const float* loop1 = (const float*)d_in[2];
  const float* b1    = (const float*)d_in[3];
  const float* W2    = (const float*)d_in[4];
  const float* loop2 = (const float*)d_in[5];
  const float* b2    = (const float*)d_in[6];
  const int*   src   = (const int*)d_in[7];
  const int*   dst   = (const int*)d_in[8];
  const int*   et    = (const int*)d_in[9];
  float* out = (float*)d_out;

  dim3 g1((N_NODES + 127) / 128, N_RELS + 1);
  k_transform1<<<g1, 256>>>(feat, W1, loop1, b1);
  k_edge1<<<(N_EDGES * 16 + 255) / 256, 256>>>(src, dst, et);
  k_layer2<<<(N_NODES + 63) / 64, 256>>>(W2, loop2, b2, out);
  k_edge2<<<(N_EDGES + 255) / 256, 256>>>(src, dst, et, out);
}

// round 4
// speedup vs baseline: 1.9701x; 1.0631x over previous
#include <cuda_runtime.h>
#include <cuda_bf16.h>
#include <cstdint>

#define N_NODES 50000
#define N_EDGES 600000
#define N_RELS  19
#define D_IN    128
#define D_HID   64
#define D_OUT   2

// Scratch (device globals — no allocation allowed in kernel_launch)
__device__ float g_T1[(size_t)N_NODES * N_RELS * D_HID];   // 243 MB
__device__ float g_h1[(size_t)N_NODES * D_HID];            // agg1 -> pre-relu h1
__device__ float g_T2[(size_t)N_NODES * N_RELS * D_OUT];   // 7.6 MB

// ===========================================================================
// Family-portable tensor-core path: ldmatrix + mma.sync (sm_80+ ISA; the
// harness ptxas targets plain sm_103, so tcgen05/"a"-features are unavailable).
// ===========================================================================
__device__ __forceinline__ uint32_t smem_u32(const void* p) {
  uint32_t a;
  asm("{ .reg .u64 t; cvta.to.shared.u64 t, %1; cvt.u32.u64 %0, t; }"
      : "=r"(a) : "l"(p));
  return a;
}

#define LDSM_X4(r, addr)                                                    \
  asm volatile("ldmatrix.sync.aligned.m8n8.x4.shared.b16 {%0,%1,%2,%3}, [%4];" \
               : "=r"((r)[0]), "=r"((r)[1]), "=r"((r)[2]), "=r"((r)[3])     \
               : "r"(addr))

#define MMA_BF16(d, a, b0, b1)                                              \
  asm volatile("mma.sync.aligned.m16n8k16.row.col.f32.bf16.bf16.f32 "       \
               "{%0,%1,%2,%3}, {%4,%5,%6,%7}, {%8,%9}, {%0,%1,%2,%3};"      \
               : "+f"((d)[0]), "+f"((d)[1]), "+f"((d)[2]), "+f"((d)[3])     \
               : "r"((a)[0]), "r"((a)[1]), "r"((a)[2]), "r"((a)[3]),        \
                 "r"(b0), "r"(b1))

// SMEM layout (halves pitch 136 = 272B rows: ldmatrix row-start banks 4g,
// conflict-free across the 8-row phases).
#define PITCH 136
#define S_AH 0
#define S_AL (128 * PITCH * 2)          // 34816
#define S_BH (S_AL + 128 * PITCH * 2)   // 69632
#define S_BL (S_BH + 64 * PITCH * 2)    // 87040
#define S_TOT (S_BL + 64 * PITCH * 2)   // 104448

__device__ __forceinline__ uint32_t pack_bf16x2(float a, float b) {
  __nv_bfloat162 h = __floats2bfloat162_rn(a, b);
  return *(uint32_t*)&h;
}

// ---------------------------------------------------------------------------
// Kernel 1 (v4): bf16 mma.sync GEMM with 3-term split (fp32-like accuracy).
// CTA = 128-node tile x 5 relation slots. A = feat tile [128n x 128k] hi/lo
// (staged once). B = W^T [64o x 128k] hi/lo (restaged per slot).
// acc[n,o] = Ah*Bh + Al*Bh + Ah*Bl, accumulated in fp32 mma accumulators.
// slot < 19 -> g_T1 ; slot == 19 -> g_h1 = feat@loop1 + b1.
// ---------------------------------------------------------------------------
__global__ void __launch_bounds__(256) k_transform1_mma(
    const float* __restrict__ feat, const float* __restrict__ W1,
    const float* __restrict__ loop1, const float* __restrict__ b1) {
  extern __shared__ char sm[];
  const uint32_t sb = smem_u32(sm);
  const int tid = threadIdx.x, wid = tid >> 5, lane = tid & 31;
  const int n0 = blockIdx.x * 128;

  // ---- Stage A: feat[n0:n0+128][0:128] as bf16 hi/lo ----
  #pragma unroll
  for (int t = 0; t < 16; t++) {
    int i = tid + t * 256;           // 4096 float4
    int n = i >> 5, kq = i & 31;
    float4 v = make_float4(0.f, 0.f, 0.f, 0.f);
    if (n0 + n < N_NODES)
      v = *(const float4*)(feat + (size_t)(n0 + n) * D_IN + kq * 4);
    float hx = __bfloat162float(__float2bfloat16_rn(v.x));
    float hy = __bfloat162float(__float2bfloat16_rn(v.y));
    float hz = __bfloat162float(__float2bfloat16_rn(v.z));
    float hw = __bfloat162float(__float2bfloat16_rn(v.w));
    uint32_t off = ((uint32_t)n * PITCH + (uint32_t)kq * 4) * 2;  // bytes
    uint2 hp, lp;
    hp.x = pack_bf16x2(hx, hy);        hp.y = pack_bf16x2(hz, hw);
    lp.x = pack_bf16x2(v.x - hx, v.y - hy);
    lp.y = pack_bf16x2(v.z - hz, v.w - hw);
    *(uint2*)(sm + S_AH + off) = hp;
    *(uint2*)(sm + S_AL + off) = lp;
  }

  // Warp tile: 4(M) x 2(N) warp grid; 32 rows x 32 cols per warp.
  const int mrow = (wid & 3) * 32;
  const int ncol = (wid >> 2) * 32;
  const int lr = lane & 15, lc = lane >> 4;
  // ldmatrix row pointers (byte offsets); k-step advance = 16 halves = 32B.
  const uint32_t aoff0 = ((uint32_t)(mrow + lr) * PITCH + (uint32_t)lc * 8) * 2;
  const uint32_t aoff1 = aoff0 + 16 * PITCH * 2;
  const uint32_t boff0 = ((uint32_t)(ncol + lr) * PITCH + (uint32_t)lc * 8) * 2;
  const uint32_t boff1 = boff0 + 16 * PITCH * 2;
  const int g = lane >> 2, tq = lane & 3;

  for (int i5 = 0; i5 < 5; i5++) {
    const int slot = blockIdx.y * 5 + i5;
    const float* __restrict__ Wb =
        (slot < N_RELS) ? W1 + (size_t)slot * (D_IN * D_HID) : loop1;

    __syncthreads();   // A ready (iter 0) / previous slot's B reads done
    // ---- Stage B = W^T as bf16 hi/lo: sB[o][k] ----
    #pragma unroll
    for (int t = 0; t < 8; t++) {
      int i = tid + t * 256;         // 2048 float4
      int k = i >> 4, o4 = i & 15;
      float4 v = *(const float4*)(Wb + (size_t)k * D_HID + o4 * 4);
      float x[4] = {v.x, v.y, v.z, v.w};
      #pragma unroll
      for (int j = 0; j < 4; j++) {
        float h = __bfloat162float(__float2bfloat16_rn(x[j]));
        uint32_t off = ((uint32_t)(o4 * 4 + j) * PITCH + (uint32_t)k) * 2;
        *(__nv_bfloat16*)(sm + S_BH + off) = __float2bfloat16_rn(h);
        *(__nv_bfloat16*)(sm + S_BL + off) = __float2bfloat16_rn(x[j] - h);
      }
    }
    __syncthreads();

    float acc[2][4][4];
    #pragma unroll
    for (int mi = 0; mi < 2; mi++)
      #pragma unroll
      for (int ni = 0; ni < 4; ni++)
        #pragma unroll
        for (int c = 0; c < 4; c++) acc[mi][ni][c] = 0.f;

    #pragma unroll
    for (int term = 0; term < 3; term++) {
      const uint32_t ab = sb + ((term == 1) ? S_AL : S_AH);
      const uint32_t bb = sb + ((term == 2) ? S_BL : S_BH);
      #pragma unroll
      for (int k0 = 0; k0 < 8; k0++) {
        const uint32_t ka = (uint32_t)k0 * 32;  // 16 halves per k-step
        uint32_t A0[4], A1[4], B0[4], B1[4];
        LDSM_X4(A0, ab + aoff0 + ka);
        LDSM_X4(A1, ab + aoff1 + ka);
        LDSM_X4(B0, bb + boff0 + ka);
        LDSM_X4(B1, bb + boff1 + ka);
        // B x4 -> two n8 fragments each: {r0,r2} and {r1,r3}
        MMA_BF16(acc[0][0], A0, B0[0], B0[2]);
        MMA_BF16(acc[0][1], A0, B0[1], B0[3]);
        MMA_BF16(acc[0][2], A0, B1[0], B1[2]);
        MMA_BF16(acc[0][3], A0, B1[1], B1[3]);
        MMA_BF16(acc[1][0], A1, B0[0], B0[2]);
        MMA_BF16(acc[1][1], A1, B0[1], B0[3]);
        MMA_BF16(acc[1][2], A1, B1[0], B1[2]);
        MMA_BF16(acc[1][3], A1, B1[1], B1[3]);
      }
    }

    // ---- Epilogue: fragment -> global ----
    #pragma unroll
    for (int mi = 0; mi < 2; mi++) {
      int r0 = n0 + mrow + mi * 16 + g;
      #pragma unroll
      for (int ni = 0; ni < 4; ni++) {
        int col = ncol + ni * 8 + tq * 2;
        if (slot < N_RELS) {
          if (r0 < N_NODES)
            *(float2*)(g_T1 + ((size_t)r0 * N_RELS + slot) * D_HID + col) =
                make_float2(acc[mi][ni][0], acc[mi][ni][1]);
          if (r0 + 8 < N_NODES)
            *(float2*)(g_T1 + ((size_t)(r0 + 8) * N_RELS + slot) * D_HID + col) =
                make_float2(acc[mi][ni][2], acc[mi][ni][3]);
        } else {
          float bx = __ldg(b1 + col), by = __ldg(b1 + col + 1);
          if (r0 < N_NODES)
            *(float2*)(g_h1 + (size_t)r0 * D_HID + col) =
                make_float2(acc[mi][ni][0] + bx, acc[mi][ni][1] + by);
          if (r0 + 8 < N_NODES)
            *(float2*)(g_h1 + (size_t)(r0 + 8) * D_HID + col) =
                make_float2(acc[mi][ni][2] + bx, acc[mi][ni][3] + by);
        }
      }
    }
  }
}

// ---------------------------------------------------------------------------
// Kernel 2: edge gather + scatter-add (layer 1). 16 threads/edge, red.v4.
// ---------------------------------------------------------------------------
__global__ void __launch_bounds__(256) k_edge1(
    const int* __restrict__ src, const int* __restrict__ dst,
    const int* __restrict__ et) {
  int idx = blockIdx.x * 256 + threadIdx.x;
  int e = idx >> 4;
  if (e >= N_EDGES) return;
  int q = idx & 15;
  int s = __ldg(src + e), d = __ldg(dst + e), r = __ldg(et + e);
  const float4 v =
      *(const float4*)(g_T1 + ((size_t)s * N_RELS + r) * D_HID + q * 4);
  float* p = g_h1 + (size_t)d * D_HID + q * 4;
  asm volatile("red.global.add.v4.f32 [%0], {%1,%2,%3,%4};"
               :: "l"(p), "f"(v.x), "f"(v.y), "f"(v.z), "f"(v.w)
               : "memory");
}

// ---------------------------------------------------------------------------
// Kernel 3: layer-2 transform + self-loop + bias (initializes d_out).
// ---------------------------------------------------------------------------
__global__ void __launch_bounds__(256) k_layer2(
    const float* __restrict__ W2, const float* __restrict__ loop2,
    const float* __restrict__ b2, float* __restrict__ out) {
  __shared__ float sH[64][65];
  __shared__ float sW[N_RELS * D_HID * D_OUT];
  __shared__ float sL[D_HID * D_OUT + D_OUT];
  const int n0 = blockIdx.x * 64;

  for (int i = threadIdx.x; i < N_RELS * D_HID * D_OUT; i += 256) sW[i] = W2[i];
  for (int i = threadIdx.x; i < D_HID * D_OUT; i += 256) sL[i] = loop2[i];
  if (threadIdx.x < D_OUT) sL[D_HID * D_OUT + threadIdx.x] = b2[threadIdx.x];
  for (int i = threadIdx.x; i < 64 * D_HID; i += 256) {
    int n = i >> 6, k = i & 63;
    float v = 0.f;
    if (n0 + n < N_NODES) v = g_h1[(size_t)(n0 + n) * D_HID + k];
    sH[n][k] = fmaxf(v, 0.f);
  }
  __syncthreads();

  const int node = threadIdx.x >> 2;
  const int rg   = threadIdx.x & 3;
  float acc[5][2] = {};
  float s0 = 0.f, s1 = 0.f;
  for (int k = 0; k < D_HID; k++) {
    float f = sH[node][k];
    #pragma unroll
    for (int i = 0; i < 5; i++) {
      int r = rg + 4 * i;
      if (r < N_RELS) {
        acc[i][0] += f * sW[(r * D_HID + k) * 2];
        acc[i][1] += f * sW[(r * D_HID + k) * 2 + 1];
      }
    }
    if (rg == 0) { s0 += f * sL[k * 2]; s1 += f * sL[k * 2 + 1]; }
  }

  int n = n0 + node;
  if (n < N_NODES) {
    #pragma unroll
    for (int i = 0; i < 5; i++) {
      int r = rg + 4 * i;
      if (r < N_RELS)
        *(float2*)&g_T2[((size_t)n * N_RELS + r) * D_OUT] =
            make_float2(acc[i][0], acc[i][1]);
    }
    if (rg == 0)
      *(float2*)&out[(size_t)n * D_OUT] =
          make_float2(s0 + sL[D_HID * D_OUT], s1 + sL[D_HID * D_OUT + 1]);
  }
}

// ---------------------------------------------------------------------------
// Kernel 4: edge gather + scatter-add (layer 2). One thread per edge.
// ---------------------------------------------------------------------------
__global__ void __launch_bounds__(256) k_edge2(
    const int* __restrict__ src, const int* __restrict__ dst,
    const int* __restrict__ et, float* __restrict__ out) {
  int e = blockIdx.x * 256 + threadIdx.x;
  if (e >= N_EDGES) return;
  int s = __ldg(src + e), d = __ldg(dst + e), r = __ldg(et + e);
  const float2 v = *(const float2*)(g_T2 + ((size_t)s * N_RELS + r) * D_OUT);
  asm volatile("red.global.add.v2.f32 [%0], {%1,%2};"
               :: "l"(out + (size_t)d * D_OUT), "f"(v.x), "f"(v.y)
               : "memory");
}

// ---------------------------------------------------------------------------
extern "C" void kernel_launch(void* const* d_in, const int* in_sizes, int n_in,
                              void* d_out, int out_size) {
  const float* feat  = (const float*)d_in[0];
  const float* W1    = (const float*)d_in[1];
  const float* loop1 = (const float*)d_in[2];
  const float* b1    = (const float*)d_in[3];
  const float* W2    = (const float*)d_in[4];
  const float* loop2 = (const float*)d_in[5];
  const float* b2    = (const float*)d_in[6];
  const int*   src   = (const int*)d_in[7];
  const int*   dst   = (const int*)d_in[8];
  const int*   et    = (const int*)d_in[9];
  float* out = (float*)d_out;

  cudaFuncSetAttribute(k_transform1_mma,
                       cudaFuncAttributeMaxDynamicSharedMemorySize, S_TOT);

  dim3 g1((N_NODES + 127) / 128, 4);   // 391 node tiles x 4 slot groups (5 each)
  k_transform1_mma<<<g1, 256, S_TOT>>>(feat, W1, loop1, b1);
  k_edge1<<<(N_EDGES * 16 + 255) / 256, 256>>>(src, dst, et);
  k_layer2<<<(N_NODES + 63) / 64, 256>>>(W2, loop2, b2, out);
  k_edge2<<<(N_EDGES + 255) / 256, 256>>>(src, dst, et, out);
}

// round 5
// speedup vs baseline: 2.1084x; 1.0702x over previous
#include <cuda_runtime.h>
#include <cuda_bf16.h>
#include <cstdint>

#define N_NODES 50000
#define N_EDGES 600000
#define N_RELS  19
#define D_IN    128
#define D_HID   64
#define D_OUT   2
#define CHUNK   128
#define MAXBLK  ((N_EDGES + CHUNK - 1) / CHUNK + N_RELS)   // 4707

// Scratch (device globals — no allocation allowed in kernel_launch)
__device__ float g_h1[(size_t)N_NODES * D_HID];            // agg1 -> pre-relu h1
__device__ float g_T2[(size_t)N_NODES * N_RELS * D_OUT];   // 7.6 MB
__device__ int   g_cnt[N_RELS];
__device__ int   g_off[N_RELS + 1];
__device__ int   g_cblk[N_RELS + 1];
__device__ int   g_fill[N_RELS];
__device__ int   g_esrc[N_EDGES];
__device__ int   g_edst[N_EDGES];

// ===========================================================================
// Family-portable tensor-core helpers (plain sm_103 target: no tcgen05).
// ===========================================================================
__device__ __forceinline__ uint32_t smem_u32(const void* p) {
  uint32_t a;
  asm("{ .reg .u64 t; cvta.to.shared.u64 t, %1; cvt.u32.u64 %0, t; }"
      : "=r"(a) : "l"(p));
  return a;
}
#define LDSM_X4(r, addr)                                                    \
  asm volatile("ldmatrix.sync.aligned.m8n8.x4.shared.b16 {%0,%1,%2,%3}, [%4];" \
               : "=r"((r)[0]), "=r"((r)[1]), "=r"((r)[2]), "=r"((r)[3])     \
               : "r"(addr))
#define MMA_BF16(d, a, b0, b1)                                              \
  asm volatile("mma.sync.aligned.m16n8k16.row.col.f32.bf16.bf16.f32 "       \
               "{%0,%1,%2,%3}, {%4,%5,%6,%7}, {%8,%9}, {%0,%1,%2,%3};"      \
               : "+f"((d)[0]), "+f"((d)[1]), "+f"((d)[2]), "+f"((d)[3])     \
               : "r"((a)[0]), "r"((a)[1]), "r"((a)[2]), "r"((a)[3]),        \
                 "r"(b0), "r"(b1))

#define PITCH 136
#define S_AH 0
#define S_AL (128 * PITCH * 2)          // 34816
#define S_BH (S_AL + 128 * PITCH * 2)   // 69632
#define S_BL (S_BH + 64 * PITCH * 2)    // 87040
#define S_GEMM (S_BL + 64 * PITCH * 2)  // 104448
#define S_SRC  S_GEMM                   // fused kernel extras
#define S_DST  (S_SRC + 512)
#define S_FTOT (S_DST + 512 + 64)       // fused kernel smem
#define OPITCH 68                       // out-stage pitch (floats); aliases A

__device__ __forceinline__ uint32_t pack_bf16x2(float a, float b) {
  __nv_bfloat162 h = __floats2bfloat162_rn(a, b);
  return *(uint32_t*)&h;
}

// ---------------------------------------------------------------------------
// Preprocessing: bucket edges by relation.
// ---------------------------------------------------------------------------
__global__ void k_zero() {
  if (threadIdx.x < N_RELS) g_cnt[threadIdx.x] = 0;
}

__global__ void __launch_bounds__(512) k_hist(const int* __restrict__ et) {
  __shared__ int lh[N_RELS];
  if (threadIdx.x < N_RELS) lh[threadIdx.x] = 0;
  __syncthreads();
  int base = blockIdx.x * 2048;
  #pragma unroll
  for (int j = 0; j < 4; j++) {
    int e = base + j * 512 + threadIdx.x;
    if (e < N_EDGES) atomicAdd(&lh[__ldg(et + e)], 1);
  }
  __syncthreads();
  if (threadIdx.x < N_RELS && lh[threadIdx.x])
    atomicAdd(&g_cnt[threadIdx.x], lh[threadIdx.x]);
}

__global__ void k_prefix() {
  if (threadIdx.x == 0) {
    int o = 0, cb = 0;
    for (int r = 0; r < N_RELS; r++) {
      g_off[r] = o; g_cblk[r] = cb; g_fill[r] = o;
      o += g_cnt[r];
      cb += (g_cnt[r] + CHUNK - 1) / CHUNK;
    }
    g_off[N_RELS] = o; g_cblk[N_RELS] = cb;
  }
}

__global__ void __launch_bounds__(512) k_scatter(
    const int* __restrict__ src, const int* __restrict__ dst,
    const int* __restrict__ et) {
  __shared__ int lh[N_RELS], lbase[N_RELS];
  if (threadIdx.x < N_RELS) lh[threadIdx.x] = 0;
  __syncthreads();
  int base = blockIdx.x * 2048;
  int r[4], s[4], d[4], idx[4];
  #pragma unroll
  for (int j = 0; j < 4; j++) {
    int e = base + j * 512 + threadIdx.x;
    r[j] = -1;
    if (e < N_EDGES) {
      r[j] = __ldg(et + e); s[j] = __ldg(src + e); d[j] = __ldg(dst + e);
      idx[j] = atomicAdd(&lh[r[j]], 1);
    }
  }
  __syncthreads();
  if (threadIdx.x < N_RELS)
    lbase[threadIdx.x] = lh[threadIdx.x]
        ? atomicAdd(&g_fill[threadIdx.x], lh[threadIdx.x]) : 0;
  __syncthreads();
  #pragma unroll
  for (int j = 0; j < 4; j++)
    if (r[j] >= 0) {
      int pos = lbase[r[j]] + idx[j];
      g_esrc[pos] = s[j]; g_edst[pos] = d[j];
    }
}

// ---------------------------------------------------------------------------
// Self-loop: g_h1 = feat @ loop1 + b1 (bf16 3-term mma, 128-node tiles).
// ---------------------------------------------------------------------------
__global__ void __launch_bounds__(256) k_selfloop(
    const float* __restrict__ feat, const float* __restrict__ loop1,
    const float* __restrict__ b1) {
  extern __shared__ char sm[];
  const uint32_t sb = smem_u32(sm);
  const int tid = threadIdx.x, wid = tid >> 5, lane = tid & 31;
  const int n0 = blockIdx.x * 128;

  #pragma unroll
  for (int t = 0; t < 16; t++) {
    int i = tid + t * 256;
    int n = i >> 5, kq = i & 31;
    float4 v = make_float4(0.f, 0.f, 0.f, 0.f);
    if (n0 + n < N_NODES)
      v = *(const float4*)(feat + (size_t)(n0 + n) * D_IN + kq * 4);
    float hx = __bfloat162float(__float2bfloat16_rn(v.x));
    float hy = __bfloat162float(__float2bfloat16_rn(v.y));
    float hz = __bfloat162float(__float2bfloat16_rn(v.z));
    float hw = __bfloat162float(__float2bfloat16_rn(v.w));
    uint32_t off = ((uint32_t)n * PITCH + (uint32_t)kq * 4) * 2;
    uint2 hp, lp;
    hp.x = pack_bf16x2(hx, hy); hp.y = pack_bf16x2(hz, hw);
    lp.x = pack_bf16x2(v.x - hx, v.y - hy);
    lp.y = pack_bf16x2(v.z - hz, v.w - hw);
    *(uint2*)(sm + S_AH + off) = hp;
    *(uint2*)(sm + S_AL + off) = lp;
  }
  #pragma unroll
  for (int t = 0; t < 8; t++) {
    int i = tid + t * 256;
    int k = i >> 4, o4 = i & 15;
    float4 v = *(const float4*)(loop1 + (size_t)k * D_HID + o4 * 4);
    float x[4] = {v.x, v.y, v.z, v.w};
    #pragma unroll
    for (int j = 0; j < 4; j++) {
      float h = __bfloat162float(__float2bfloat16_rn(x[j]));
      uint32_t off = ((uint32_t)(o4 * 4 + j) * PITCH + (uint32_t)k) * 2;
      *(__nv_bfloat16*)(sm + S_BH + off) = __float2bfloat16_rn(h);
      *(__nv_bfloat16*)(sm + S_BL + off) = __float2bfloat16_rn(x[j] - h);
    }
  }
  __syncthreads();

  const int mrow = (wid & 3) * 32, ncol = (wid >> 2) * 32;
  const int lr = lane & 15, lc = lane >> 4;
  const uint32_t aoff0 = ((uint32_t)(mrow + lr) * PITCH + (uint32_t)lc * 8) * 2;
  const uint32_t aoff1 = aoff0 + 16 * PITCH * 2;
  const uint32_t boff0 = ((uint32_t)(ncol + lr) * PITCH + (uint32_t)lc * 8) * 2;
  const uint32_t boff1 = boff0 + 16 * PITCH * 2;
  const int g = lane >> 2, tq = lane & 3;

  float acc[2][4][4];
  #pragma unroll
  for (int mi = 0; mi < 2; mi++)
    #pragma unroll
    for (int ni = 0; ni < 4; ni++)
      #pragma unroll
      for (int c = 0; c < 4; c++) acc[mi][ni][c] = 0.f;

  #pragma unroll
  for (int term = 0; term < 3; term++) {
    const uint32_t ab = sb + ((term == 1) ? S_AL : S_AH);
    const uint32_t bb = sb + ((term == 2) ? S_BL : S_BH);
    #pragma unroll
    for (int k0 = 0; k0 < 8; k0++) {
      const uint32_t ka = (uint32_t)k0 * 32;
      uint32_t A0[4], A1[4], B0[4], B1[4];
      LDSM_X4(A0, ab + aoff0 + ka);
      LDSM_X4(A1, ab + aoff1 + ka);
      LDSM_X4(B0, bb + boff0 + ka);
      LDSM_X4(B1, bb + boff1 + ka);
      MMA_BF16(acc[0][0], A0, B0[0], B0[2]);
      MMA_BF16(acc[0][1], A0, B0[1], B0[3]);
      MMA_BF16(acc[0][2], A0, B1[0], B1[2]);
      MMA_BF16(acc[0][3], A0, B1[1], B1[3]);
      MMA_BF16(acc[1][0], A1, B0[0], B0[2]);
      MMA_BF16(acc[1][1], A1, B0[1], B0[3]);
      MMA_BF16(acc[1][2], A1, B1[0], B1[2]);
      MMA_BF16(acc[1][3], A1, B1[1], B1[3]);
    }
  }

  #pragma unroll
  for (int mi = 0; mi < 2; mi++) {
    int r0 = n0 + mrow + mi * 16 + g;
    #pragma unroll
    for (int ni = 0; ni < 4; ni++) {
      int col = ncol + ni * 8 + tq * 2;
      float bx = __ldg(b1 + col), by = __ldg(b1 + col + 1);
      if (r0 < N_NODES)
        *(float2*)(g_h1 + (size_t)r0 * D_HID + col) =
            make_float2(acc[mi][ni][0] + bx, acc[mi][ni][1] + by);
      if (r0 + 8 < N_NODES)
        *(float2*)(g_h1 + (size_t)(r0 + 8) * D_HID + col) =
            make_float2(acc[mi][ni][2] + bx, acc[mi][ni][3] + by);
    }
  }
}

// ---------------------------------------------------------------------------
// Fused layer-1 edge GEMM: block = 128 edges of one relation.
// A = feat[src[e]] rows (L2-resident gather) hi/lo bf16; B = W1[r]^T hi/lo.
// Result staged in smem (aliases A), then red.global.add.v4 into g_h1[dst].
// ---------------------------------------------------------------------------
__global__ void __launch_bounds__(256) k_edge1_fused(
    const float* __restrict__ feat, const float* __restrict__ W1) {
  extern __shared__ char sm[];
  const uint32_t sb = smem_u32(sm);
  int* s_src = (int*)(sm + S_SRC);
  int* s_dst = (int*)(sm + S_DST);
  __shared__ int s_meta[3];
  const int tid = threadIdx.x, wid = tid >> 5, lane = tid & 31;

  if (tid == 0) {
    int b = blockIdx.x, rr = 0;
    while (rr < N_RELS && b >= g_cblk[rr + 1]) rr++;
    if (b >= g_cblk[N_RELS]) rr = -1;
    s_meta[0] = rr;
    if (rr >= 0) {
      int chunk = b - g_cblk[rr];
      int e0 = g_off[rr] + chunk * CHUNK;
      s_meta[1] = e0;
      s_meta[2] = min(CHUNK, g_off[rr] + g_cnt[rr] - e0);
    }
  }
  __syncthreads();
  const int r = s_meta[0];
  if (r < 0) return;
  const int e0 = s_meta[1], m = s_meta[2];

  if (tid < CHUNK) {
    if (tid < m) { s_src[tid] = g_esrc[e0 + tid]; s_dst[tid] = g_edst[e0 + tid]; }
    else         { s_src[tid] = -1; s_dst[tid] = -1; }
  }

  // Stage B = W1[r]^T hi/lo
  const float* __restrict__ Wb = W1 + (size_t)r * (D_IN * D_HID);
  #pragma unroll
  for (int t = 0; t < 8; t++) {
    int i = tid + t * 256;
    int k = i >> 4, o4 = i & 15;
    float4 v = *(const float4*)(Wb + (size_t)k * D_HID + o4 * 4);
    float x[4] = {v.x, v.y, v.z, v.w};
    #pragma unroll
    for (int j = 0; j < 4; j++) {
      float h = __bfloat162float(__float2bfloat16_rn(x[j]));
      uint32_t off = ((uint32_t)(o4 * 4 + j) * PITCH + (uint32_t)k) * 2;
      *(__nv_bfloat16*)(sm + S_BH + off) = __float2bfloat16_rn(h);
      *(__nv_bfloat16*)(sm + S_BL + off) = __float2bfloat16_rn(x[j] - h);
    }
  }
  __syncthreads();   // s_src visible

  // Gather A rows = feat[src[i]] hi/lo
  #pragma unroll
  for (int t = 0; t < 16; t++) {
    int i = tid + t * 256;
    int row = i >> 5, kq = i & 31;
    int s = s_src[row];
    float4 v = make_float4(0.f, 0.f, 0.f, 0.f);
    if (s >= 0) v = *(const float4*)(feat + (size_t)s * D_IN + kq * 4);
    float hx = __bfloat162float(__float2bfloat16_rn(v.x));
    float hy = __bfloat162float(__float2bfloat16_rn(v.y));
    float hz = __bfloat162float(__float2bfloat16_rn(v.z));
    float hw = __bfloat162float(__float2bfloat16_rn(v.w));
    uint32_t off = ((uint32_t)row * PITCH + (uint32_t)kq * 4) * 2;
    uint2 hp, lp;
    hp.x = pack_bf16x2(hx, hy); hp.y = pack_bf16x2(hz, hw);
    lp.x = pack_bf16x2(v.x - hx, v.y - hy);
    lp.y = pack_bf16x2(v.z - hz, v.w - hw);
    *(uint2*)(sm + S_AH + off) = hp;
    *(uint2*)(sm + S_AL + off) = lp;
  }
  __syncthreads();

  const int mrow = (wid & 3) * 32, ncol = (wid >> 2) * 32;
  const int lr = lane & 15, lc = lane >> 4;
  const uint32_t aoff0 = ((uint32_t)(mrow + lr) * PITCH + (uint32_t)lc * 8) * 2;
  const uint32_t aoff1 = aoff0 + 16 * PITCH * 2;
  const uint32_t boff0 = ((uint32_t)(ncol + lr) * PITCH + (uint32_t)lc * 8) * 2;
  const uint32_t boff1 = boff0 + 16 * PITCH * 2;
  const int g = lane >> 2, tq = lane & 3;

  float acc[2][4][4];
  #pragma unroll
  for (int mi = 0; mi < 2; mi++)
    #pragma unroll
    for (int ni = 0; ni < 4; ni++)
      #pragma unroll
      for (int c = 0; c < 4; c++) acc[mi][ni][c] = 0.f;

  #pragma unroll
  for (int term = 0; term < 3; term++) {
    const uint32_t ab = sb + ((term == 1) ? S_AL : S_AH);
    const uint32_t bb = sb + ((term == 2) ? S_BL : S_BH);
    #pragma unroll
    for (int k0 = 0; k0 < 8; k0++) {
      const uint32_t ka = (uint32_t)k0 * 32;
      uint32_t A0[4], A1[4], B0[4], B1[4];
      LDSM_X4(A0, ab + aoff0 + ka);
      LDSM_X4(A1, ab + aoff1 + ka);
      LDSM_X4(B0, bb + boff0 + ka);
      LDSM_X4(B1, bb + boff1 + ka);
      MMA_BF16(acc[0][0], A0, B0[0], B0[2]);
      MMA_BF16(acc[0][1], A0, B0[1], B0[3]);
      MMA_BF16(acc[0][2], A0, B1[0], B1[2]);
      MMA_BF16(acc[0][3], A0, B1[1], B1[3]);
      MMA_BF16(acc[1][0], A1, B0[0], B0[2]);
      MMA_BF16(acc[1][1], A1, B0[1], B0[3]);
      MMA_BF16(acc[1][2], A1, B1[0], B1[2]);
      MMA_BF16(acc[1][3], A1, B1[1], B1[3]);
    }
  }
  __syncthreads();   // all ldmatrix reads of A done before aliasing

  // Stage result over A region, then vectorized scatter-add.
  float* sout = (float*)sm;   // [128][OPITCH]
  #pragma unroll
  for (int mi = 0; mi < 2; mi++) {
    int row = mrow + mi * 16 + g;
    #pragma unroll
    for (int ni = 0; ni < 4; ni++) {
      int col = ncol + ni * 8 + tq * 2;
      *(float2*)&sout[row * OPITCH + col] =
          make_float2(acc[mi][ni][0], acc[mi][ni][1]);
      *(float2*)&sout[(row + 8) * OPITCH + col] =
          make_float2(acc[mi][ni][2], acc[mi][ni][3]);
    }
  }
  __syncthreads();

  #pragma unroll
  for (int t = 0; t < 8; t++) {
    int i = (tid + t * 256) >> 4, q = tid & 15;
    if (i < m) {
      int d = s_dst[i];
      float4 v = *(const float4*)&sout[i * OPITCH + q * 4];
      float* p = g_h1 + (size_t)d * D_HID + q * 4;
      asm volatile("red.global.add.v4.f32 [%0], {%1,%2,%3,%4};"
                   :: "l"(p), "f"(v.x), "f"(v.y), "f"(v.z), "f"(v.w)
                   : "memory");
    }
  }
}

// ---------------------------------------------------------------------------
// Layer 2 (unchanged): per-node transform + self-loop, then edge reduce.
// ---------------------------------------------------------------------------
__global__ void __launch_bounds__(256) k_layer2(
    const float* __restrict__ W2, const float* __restrict__ loop2,
    const float* __restrict__ b2, float* __restrict__ out) {
  __shared__ float sH[64][65];
  __shared__ float sW[N_RELS * D_HID * D_OUT];
  __shared__ float sL[D_HID * D_OUT + D_OUT];
  const int n0 = blockIdx.x * 64;

  for (int i = threadIdx.x; i < N_RELS * D_HID * D_OUT; i += 256) sW[i] = W2[i];
  for (int i = threadIdx.x; i < D_HID * D_OUT; i += 256) sL[i] = loop2[i];
  if (threadIdx.x < D_OUT) sL[D_HID * D_OUT + threadIdx.x] = b2[threadIdx.x];
  for (int i = threadIdx.x; i < 64 * D_HID; i += 256) {
    int n = i >> 6, k = i & 63;
    float v = 0.f;
    if (n0 + n < N_NODES) v = g_h1[(size_t)(n0 + n) * D_HID + k];
    sH[n][k] = fmaxf(v, 0.f);
  }
  __syncthreads();

  const int node = threadIdx.x >> 2;
  const int rg   = threadIdx.x & 3;
  float acc[5][2] = {};
  float s0 = 0.f, s1 = 0.f;
  for (int k = 0; k < D_HID; k++) {
    float f = sH[node][k];
    #pragma unroll
    for (int i = 0; i < 5; i++) {
      int r = rg + 4 * i;
      if (r < N_RELS) {
        acc[i][0] += f * sW[(r * D_HID + k) * 2];
        acc[i][1] += f * sW[(r * D_HID + k) * 2 + 1];
      }
    }
    if (rg == 0) { s0 += f * sL[k * 2]; s1 += f * sL[k * 2 + 1]; }
  }

  int n = n0 + node;
  if (n < N_NODES) {
    #pragma unroll
    for (int i = 0; i < 5; i++) {
      int r = rg + 4 * i;
      if (r < N_RELS)
        *(float2*)&g_T2[((size_t)n * N_RELS + r) * D_OUT] =
            make_float2(acc[i][0], acc[i][1]);
    }
    if (rg == 0)
      *(float2*)&out[(size_t)n * D_OUT] =
          make_float2(s0 + sL[D_HID * D_OUT], s1 + sL[D_HID * D_OUT + 1]);
  }
}

__global__ void __launch_bounds__(256) k_edge2(
    const int* __restrict__ src, const int* __restrict__ dst,
    const int* __restrict__ et, float* __restrict__ out) {
  int e = blockIdx.x * 256 + threadIdx.x;
  if (e >= N_EDGES) return;
  int s = __ldg(src + e), d = __ldg(dst + e), r = __ldg(et + e);
  const float2 v = *(const float2*)(g_T2 + ((size_t)s * N_RELS + r) * D_OUT);
  asm volatile("red.global.add.v2.f32 [%0], {%1,%2};"
               :: "l"(out + (size_t)d * D_OUT), "f"(v.x), "f"(v.y)
               : "memory");
}

// ---------------------------------------------------------------------------
extern "C" void kernel_launch(void* const* d_in, const int* in_sizes, int n_in,
                              void* d_out, int out_size) {
  const float* feat  = (const float*)d_in[0];
  const float* W1    = (const float*)d_in[1];
  const float* loop1 = (const float*)d_in[2];
  const float* b1    = (const float*)d_in[3];
  const float* W2    = (const float*)d_in[4];
  const float* loop2 = (const float*)d_in[5];
  const float* b2    = (const float*)d_in[6];
  const int*   src   = (const int*)d_in[7];
  const int*   dst   = (const int*)d_in[8];
  const int*   et    = (const int*)d_in[9];
  float* out = (float*)d_out;

  cudaFuncSetAttribute(k_selfloop,
                       cudaFuncAttributeMaxDynamicSharedMemorySize, S_GEMM);
  cudaFuncSetAttribute(k_edge1_fused,
                       cudaFuncAttributeMaxDynamicSharedMemorySize, S_FTOT);

  // Edge bucketing by relation
  k_zero<<<1, 32>>>();
  k_hist<<<(N_EDGES + 2047) / 2048, 512>>>(et);
  k_prefix<<<1, 32>>>();
  k_scatter<<<(N_EDGES + 2047) / 2048, 512>>>(src, dst, et);

  // Layer 1
  k_selfloop<<<(N_NODES + 127) / 128, 256, S_GEMM>>>(feat, loop1, b1);
  k_edge1_fused<<<MAXBLK, 256, S_FTOT>>>(feat, W1);

  // Layer 2
  k_layer2<<<(N_NODES + 63) / 64, 256>>>(W2, loop2, b2, out);
  k_edge2<<<(N_EDGES + 255) / 256, 256>>>(src, dst, et, out);
}

// round 6
// speedup vs baseline: 3.0086x; 1.4269x over previous
#include <cuda_runtime.h>
#include <cuda_bf16.h>
#include <cstdint>

#define N_NODES 50000
#define N_EDGES 600000
#define N_RELS  19
#define D_IN    128
#define D_HID   64
#define D_OUT   2
#define CHUNK   128
#define MAXBLK  ((N_EDGES + CHUNK - 1) / CHUNK + N_RELS)   // 4707

// Scratch (device globals — no allocation allowed in kernel_launch)
__device__ float g_h1[(size_t)N_NODES * D_HID];
__device__ float g_T2[(size_t)N_NODES * N_RELS * D_OUT];
__device__ int   g_cnt[N_RELS];
__device__ int   g_off[N_RELS + 1];
__device__ int   g_cblk[N_RELS + 1];
__device__ int   g_fill[N_RELS];
__device__ int   g_done;
__device__ int   g_esrc[N_EDGES];
__device__ int   g_edst[N_EDGES];
// Preconverted bf16 hi/lo operands
__device__ __align__(256) __nv_bfloat16 g_featH[(size_t)N_NODES * D_IN];
__device__ __align__(256) __nv_bfloat16 g_featL[(size_t)N_NODES * D_IN];
// W images in exact smem layout: per rel [hi plane 64x136][lo plane 64x136];
// rel 19 = loop1.
#define PITCH 136
#define WIMG_HALVES (2 * 64 * PITCH)    // 17408 halves = 34816 B per rel
__device__ __align__(256) __nv_bfloat16 g_wimg[20 * WIMG_HALVES];

// ===========================================================================
__device__ __forceinline__ uint32_t smem_u32(const void* p) {
  uint32_t a;
  asm("{ .reg .u64 t; cvta.to.shared.u64 t, %1; cvt.u32.u64 %0, t; }"
      : "=r"(a) : "l"(p));
  return a;
}
#define LDSM_X4(r, addr)                                                    \
  asm volatile("ldmatrix.sync.aligned.m8n8.x4.shared.b16 {%0,%1,%2,%3}, [%4];" \
               : "=r"((r)[0]), "=r"((r)[1]), "=r"((r)[2]), "=r"((r)[3])     \
               : "r"(addr))
#define MMA_BF16(d, a, b0, b1)                                              \
  asm volatile("mma.sync.aligned.m16n8k16.row.col.f32.bf16.bf16.f32 "       \
               "{%0,%1,%2,%3}, {%4,%5,%6,%7}, {%8,%9}, {%0,%1,%2,%3};"      \
               : "+f"((d)[0]), "+f"((d)[1]), "+f"((d)[2]), "+f"((d)[3])     \
               : "r"((a)[0]), "r"((a)[1]), "r"((a)[2]), "r"((a)[3]),        \
                 "r"(b0), "r"(b1))
#define CP16(dst, src)                                                      \
  asm volatile("cp.async.cg.shared.global [%0], [%1], 16;"                  \
               :: "r"(dst), "l"(src) : "memory")
#define CP_COMMIT() asm volatile("cp.async.commit_group;" ::: "memory")
#define CP_WAIT0()  asm volatile("cp.async.wait_group 0;" ::: "memory")

// SMEM layout (bytes); rows are 272B (PITCH halves) — ldmatrix conflict-free.
#define S_AH 0
#define S_AL (128 * PITCH * 2)          // 34816
#define S_BH (S_AL + 128 * PITCH * 2)   // 69632 ; B image hi||lo contiguous
#define S_GEMM (S_BH + WIMG_HALVES * 2) // 104448
#define S_SRC  S_GEMM
#define S_DST  (S_SRC + 512)
#define S_FTOT (S_DST + 512)
#define OPITCH 68

// ---------------------------------------------------------------------------
// Prep: feat -> bf16 hi/lo; W1+loop1 -> padded images; zero g_h1 + counters.
// ---------------------------------------------------------------------------
#define FEAT_F4 (N_NODES * 32)          // 1,600,000
#define W_F4    (20 * 2048)             // 40,960
#define H1_F4   (N_NODES * D_HID / 4)   // 800,000
#define PREP_TOT (FEAT_F4 + W_F4 + H1_F4)

__global__ void __launch_bounds__(256) k_prep(
    const float* __restrict__ feat, const float* __restrict__ W1,
    const float* __restrict__ loop1) {
  int i = blockIdx.x * 256 + threadIdx.x;
  if (i < 21) {                        // zero counters
    if (i < N_RELS) g_cnt[i] = 0;
    if (i == 20) g_done = 0;
  }
  if (i < FEAT_F4) {
    float4 v = *(const float4*)(feat + (size_t)i * 4);
    __nv_bfloat16 h[4], l[4];
    float x[4] = {v.x, v.y, v.z, v.w};
    #pragma unroll
    for (int j = 0; j < 4; j++) {
      h[j] = __float2bfloat16_rn(x[j]);
      l[j] = __float2bfloat16_rn(x[j] - __bfloat162float(h[j]));
    }
    *(uint2*)(g_featH + (size_t)i * 4) = *(uint2*)h;
    *(uint2*)(g_featL + (size_t)i * 4) = *(uint2*)l;
  } else if (i < FEAT_F4 + W_F4) {
    int j = i - FEAT_F4;
    int rel = j >> 11, rem = j & 2047;
    int k = rem >> 4, o4 = rem & 15;
    const float* srcp = (rel < N_RELS) ? (W1 + ((size_t)rel * D_IN + k) * D_HID)
                                       : (loop1 + (size_t)k * D_HID);
    float4 v = *(const float4*)(srcp + o4 * 4);
    float x[4] = {v.x, v.y, v.z, v.w};
    __nv_bfloat16* img = g_wimg + (size_t)rel * WIMG_HALVES;
    #pragma unroll
    for (int jj = 0; jj < 4; jj++) {
      int o = o4 * 4 + jj;
      __nv_bfloat16 h = __float2bfloat16_rn(x[jj]);
      img[o * PITCH + k] = h;
      img[64 * PITCH + o * PITCH + k] =
          __float2bfloat16_rn(x[jj] - __bfloat162float(h));
    }
  } else if (i < PREP_TOT) {
    int j = i - FEAT_F4 - W_F4;
    *(float4*)(g_h1 + (size_t)j * 4) = make_float4(0.f, 0.f, 0.f, 0.f);
  }
}

// ---------------------------------------------------------------------------
// Hist + prefix (done-counter; last block computes offsets).
// ---------------------------------------------------------------------------
__global__ void __launch_bounds__(512) k_histprefix(const int* __restrict__ et) {
  __shared__ int lh[N_RELS];
  if (threadIdx.x < N_RELS) lh[threadIdx.x] = 0;
  __syncthreads();
  int base = blockIdx.x * 2048;
  #pragma unroll
  for (int j = 0; j < 4; j++) {
    int e = base + j * 512 + threadIdx.x;
    if (e < N_EDGES) atomicAdd(&lh[__ldg(et + e)], 1);
  }
  __syncthreads();
  if (threadIdx.x < N_RELS && lh[threadIdx.x])
    atomicAdd(&g_cnt[threadIdx.x], lh[threadIdx.x]);
  __threadfence();
  __syncthreads();
  if (threadIdx.x == 0) {
    int old = atomicAdd(&g_done, 1);
    if (old == (int)gridDim.x - 1) {
      int o = 0, cb = 0;
      for (int r = 0; r < N_RELS; r++) {
        g_off[r] = o; g_cblk[r] = cb; g_fill[r] = o;
        o += g_cnt[r];
        cb += (g_cnt[r] + CHUNK - 1) / CHUNK;
      }
      g_off[N_RELS] = o; g_cblk[N_RELS] = cb;
    }
  }
}

__global__ void __launch_bounds__(512) k_scatter(
    const int* __restrict__ src, const int* __restrict__ dst,
    const int* __restrict__ et) {
  __shared__ int lh[N_RELS], lbase[N_RELS];
  if (threadIdx.x < N_RELS) lh[threadIdx.x] = 0;
  __syncthreads();
  int base = blockIdx.x * 2048;
  int r[4], s[4], d[4], idx[4];
  #pragma unroll
  for (int j = 0; j < 4; j++) {
    int e = base + j * 512 + threadIdx.x;
    r[j] = -1;
    if (e < N_EDGES) {
      r[j] = __ldg(et + e); s[j] = __ldg(src + e); d[j] = __ldg(dst + e);
      idx[j] = atomicAdd(&lh[r[j]], 1);
    }
  }
  __syncthreads();
  if (threadIdx.x < N_RELS)
    lbase[threadIdx.x] = lh[threadIdx.x]
        ? atomicAdd(&g_fill[threadIdx.x], lh[threadIdx.x]) : 0;
  __syncthreads();
  #pragma unroll
  for (int j = 0; j < 4; j++)
    if (r[j] >= 0) {
      int pos = lbase[r[j]] + idx[j];
      g_esrc[pos] = s[j]; g_edst[pos] = d[j];
    }
}

// ---------------------------------------------------------------------------
// Shared MMA core: A/B already staged in smem; returns acc.
// ---------------------------------------------------------------------------
__device__ __forceinline__ void mma_core(uint32_t sb, int wid, int lane,
                                         float acc[2][4][4]) {
  const int mrow = (wid & 3) * 32, ncol = (wid >> 2) * 32;
  const int lr = lane & 15, lc = lane >> 4;
  const uint32_t aoff0 = ((uint32_t)(mrow + lr) * PITCH + (uint32_t)lc * 8) * 2;
  const uint32_t aoff1 = aoff0 + 16 * PITCH * 2;
  const uint32_t boff0 = ((uint32_t)(ncol + lr) * PITCH + (uint32_t)lc * 8) * 2;
  const uint32_t boff1 = boff0 + 16 * PITCH * 2;
  #pragma unroll
  for (int mi = 0; mi < 2; mi++)
    #pragma unroll
    for (int ni = 0; ni < 4; ni++)
      #pragma unroll
      for (int c = 0; c < 4; c++) acc[mi][ni][c] = 0.f;
  #pragma unroll
  for (int term = 0; term < 3; term++) {
    const uint32_t ab = sb + ((term == 1) ? S_AL : S_AH);
    const uint32_t bb = sb + S_BH + ((term == 2) ? 64 * PITCH * 2 : 0);
    #pragma unroll
    for (int k0 = 0; k0 < 8; k0++) {
      const uint32_t ka = (uint32_t)k0 * 32;
      uint32_t A0[4], A1[4], B0[4], B1[4];
      LDSM_X4(A0, ab + aoff0 + ka);
      LDSM_X4(A1, ab + aoff1 + ka);
      LDSM_X4(B0, bb + boff0 + ka);
      LDSM_X4(B1, bb + boff1 + ka);
      MMA_BF16(acc[0][0], A0, B0[0], B0[2]);
      MMA_BF16(acc[0][1], A0, B0[1], B0[3]);
      MMA_BF16(acc[0][2], A0, B1[0], B1[2]);
      MMA_BF16(acc[0][3], A0, B1[1], B1[3]);
      MMA_BF16(acc[1][0], A1, B0[0], B0[2]);
      MMA_BF16(acc[1][1], A1, B0[1], B0[3]);
      MMA_BF16(acc[1][2], A1, B1[0], B1[2]);
      MMA_BF16(acc[1][3], A1, B1[1], B1[3]);
    }
  }
}

// ---------------------------------------------------------------------------
// Fused layer-1 edge GEMM: 128 edges of one relation per block.
// All staging via cp.async of preconverted bf16 operands.
// ---------------------------------------------------------------------------
__global__ void __launch_bounds__(256) k_edge1_fused() {
  extern __shared__ char sm[];
  const uint32_t sb = smem_u32(sm);
  int* s_src = (int*)(sm + S_SRC);
  int* s_dst = (int*)(sm + S_DST);
  __shared__ int s_meta[3];
  const int tid = threadIdx.x, wid = tid >> 5, lane = tid & 31;

  if (tid == 0) {
    int b = blockIdx.x, rr = 0;
    while (rr < N_RELS && b >= g_cblk[rr + 1]) rr++;
    if (b >= g_cblk[N_RELS]) rr = -1;
    s_meta[0] = rr;
    if (rr >= 0) {
      int chunk = b - g_cblk[rr];
      int e0 = g_off[rr] + chunk * CHUNK;
      s_meta[1] = e0;
      s_meta[2] = min(CHUNK, g_off[rr] + g_cnt[rr] - e0);
    }
  }
  __syncthreads();
  const int r = s_meta[0];
  if (r < 0) return;
  const int e0 = s_meta[1], m = s_meta[2];

  if (tid < CHUNK) {
    if (tid < m) { s_src[tid] = g_esrc[e0 + tid]; s_dst[tid] = g_edst[e0 + tid]; }
    else         { s_src[tid] = 0;  s_dst[tid] = -1; }
  }

  // B image copy: 2176 x 16B (hi||lo planes, exact smem layout).
  const char* wsrc = (const char*)(g_wimg + (size_t)r * WIMG_HALVES);
  #pragma unroll
  for (int t = 0; t < 9; t++) {
    int idx = tid + t * 256;
    if (idx < WIMG_HALVES * 2 / 16)
      CP16(sb + S_BH + idx * 16, wsrc + idx * 16);
  }
  __syncthreads();   // s_src visible before A gather

  // A gather: 128 rows x (16 hi + 16 lo) 16B chunks.
  #pragma unroll
  for (int t = 0; t < 16; t++) {
    int idx = tid + t * 256;
    int row = idx >> 5, c = idx & 31;
    int s = s_src[row];
    if (c < 16)
      CP16(sb + S_AH + row * (PITCH * 2) + c * 16,
           (const char*)g_featH + (size_t)s * 256 + c * 16);
    else
      CP16(sb + S_AL + row * (PITCH * 2) + (c - 16) * 16,
           (const char*)g_featL + (size_t)s * 256 + (c - 16) * 16);
  }
  CP_COMMIT();
  CP_WAIT0();
  __syncthreads();

  float acc[2][4][4];
  mma_core(sb, wid, lane, acc);
  __syncthreads();   // A reads done before aliasing

  // Stage result over A region, vectorized scatter-add.
  float* sout = (float*)sm;
  const int g = lane >> 2, tq = lane & 3;
  const int mrow = (wid & 3) * 32, ncol = (wid >> 2) * 32;
  #pragma unroll
  for (int mi = 0; mi < 2; mi++) {
    int row = mrow + mi * 16 + g;
    #pragma unroll
    for (int ni = 0; ni < 4; ni++) {
      int col = ncol + ni * 8 + tq * 2;
      *(float2*)&sout[row * OPITCH + col] =
          make_float2(acc[mi][ni][0], acc[mi][ni][1]);
      *(float2*)&sout[(row + 8) * OPITCH + col] =
          make_float2(acc[mi][ni][2], acc[mi][ni][3]);
    }
  }
  __syncthreads();

  #pragma unroll
  for (int t = 0; t < 8; t++) {
    int i = (tid + t * 256) >> 4, q = tid & 15;
    if (i < m) {
      int d = s_dst[i];
      float4 v = *(const float4*)&sout[i * OPITCH + q * 4];
      float* p = g_h1 + (size_t)d * D_HID + q * 4;
      asm volatile("red.global.add.v4.f32 [%0], {%1,%2,%3,%4};"
                   :: "l"(p), "f"(v.x), "f"(v.y), "f"(v.z), "f"(v.w)
                   : "memory");
    }
  }
}

// ---------------------------------------------------------------------------
// Self-loop: red-add (feat @ loop1 + b1) into zero-init g_h1.
// ---------------------------------------------------------------------------
__global__ void __launch_bounds__(256) k_selfloop(const float* __restrict__ b1) {
  extern __shared__ char sm[];
  const uint32_t sb = smem_u32(sm);
  const int tid = threadIdx.x, wid = tid >> 5, lane = tid & 31;
  const int n0 = blockIdx.x * 128;

  const char* wsrc = (const char*)(g_wimg + (size_t)N_RELS * WIMG_HALVES);
  #pragma unroll
  for (int t = 0; t < 9; t++) {
    int idx = tid + t * 256;
    if (idx < WIMG_HALVES * 2 / 16)
      CP16(sb + S_BH + idx * 16, wsrc + idx * 16);
  }
  #pragma unroll
  for (int t = 0; t < 16; t++) {
    int idx = tid + t * 256;
    int row = idx >> 5, c = idx & 31;
    int n = min(n0 + row, N_NODES - 1);
    if (c < 16)
      CP16(sb + S_AH + row * (PITCH * 2) + c * 16,
           (const char*)g_featH + (size_t)n * 256 + c * 16);
    else
      CP16(sb + S_AL + row * (PITCH * 2) + (c - 16) * 16,
           (const char*)g_featL + (size_t)n * 256 + (c - 16) * 16);
  }
  CP_COMMIT();
  CP_WAIT0();
  __syncthreads();

  float acc[2][4][4];
  mma_core(sb, wid, lane, acc);

  const int g = lane >> 2, tq = lane & 3;
  const int mrow = (wid & 3) * 32, ncol = (wid >> 2) * 32;
  #pragma unroll
  for (int mi = 0; mi < 2; mi++) {
    int r0 = n0 + mrow + mi * 16 + g;
    #pragma unroll
    for (int ni = 0; ni < 4; ni++) {
      int col = ncol + ni * 8 + tq * 2;
      float bx = __ldg(b1 + col), by = __ldg(b1 + col + 1);
      if (r0 < N_NODES)
        asm volatile("red.global.add.v2.f32 [%0], {%1,%2};"
                     :: "l"(g_h1 + (size_t)r0 * D_HID + col),
                        "f"(acc[mi][ni][0] + bx), "f"(acc[mi][ni][1] + by)
                     : "memory");
      if (r0 + 8 < N_NODES)
        asm volatile("red.global.add.v2.f32 [%0], {%1,%2};"
                     :: "l"(g_h1 + (size_t)(r0 + 8) * D_HID + col),
                        "f"(acc[mi][ni][2] + bx), "f"(acc[mi][ni][3] + by)
                     : "memory");
    }
  }
}

// ---------------------------------------------------------------------------
// Layer 2 (unchanged) + edge2.
// ---------------------------------------------------------------------------
__global__ void __launch_bounds__(256) k_layer2(
    const float* __restrict__ W2, const float* __restrict__ loop2,
    const float* __restrict__ b2, float* __restrict__ out) {
  __shared__ float sH[64][65];
  __shared__ float sW[N_RELS * D_HID * D_OUT];
  __shared__ float sL[D_HID * D_OUT + D_OUT];
  const int n0 = blockIdx.x * 64;

  for (int i = threadIdx.x; i < N_RELS * D_HID * D_OUT; i += 256) sW[i] = W2[i];
  for (int i = threadIdx.x; i < D_HID * D_OUT; i += 256) sL[i] = loop2[i];
  if (threadIdx.x < D_OUT) sL[D_HID * D_OUT + threadIdx.x] = b2[threadIdx.x];
  for (int i = threadIdx.x; i < 64 * D_HID; i += 256) {
    int n = i >> 6, k = i & 63;
    float v = 0.f;
    if (n0 + n < N_NODES) v = g_h1[(size_t)(n0 + n) * D_HID + k];
    sH[n][k] = fmaxf(v, 0.f);
  }
  __syncthreads();

  const int node = threadIdx.x >> 2;
  const int rg   = threadIdx.x & 3;
  float acc[5][2] = {};
  float s0 = 0.f, s1 = 0.f;
  for (int k = 0; k < D_HID; k++) {
    float f = sH[node][k];
    #pragma unroll
    for (int i = 0; i < 5; i++) {
      int r = rg + 4 * i;
      if (r < N_RELS) {
        acc[i][0] += f * sW[(r * D_HID + k) * 2];
        acc[i][1] += f * sW[(r * D_HID + k) * 2 + 1];
      }
    }
    if (rg == 0) { s0 += f * sL[k * 2]; s1 += f * sL[k * 2 + 1]; }
  }

  int n = n0 + node;
  if (n < N_NODES) {
    #pragma unroll
    for (int i = 0; i < 5; i++) {
      int r = rg + 4 * i;
      if (r < N_RELS)
        *(float2*)&g_T2[((size_t)n * N_RELS + r) * D_OUT] =
            make_float2(acc[i][0], acc[i][1]);
    }
    if (rg == 0)
      *(float2*)&out[(size_t)n * D_OUT] =
          make_float2(s0 + sL[D_HID * D_OUT], s1 + sL[D_HID * D_OUT + 1]);
  }
}

__global__ void __launch_bounds__(256) k_edge2(
    const int* __restrict__ src, const int* __restrict__ dst,
    const int* __restrict__ et, float* __restrict__ out) {
  int e = blockIdx.x * 256 + threadIdx.x;
  if (e >= N_EDGES) return;
  int s = __ldg(src + e), d = __ldg(dst + e), r = __ldg(et + e);
  const float2 v = *(const float2*)(g_T2 + ((size_t)s * N_RELS + r) * D_OUT);
  asm volatile("red.global.add.v2.f32 [%0], {%1,%2};"
               :: "l"(out + (size_t)d * D_OUT), "f"(v.x), "f"(v.y)
               : "memory");
}

// ---------------------------------------------------------------------------
extern "C" void kernel_launch(void* const* d_in, const int* in_sizes, int n_in,
                              void* d_out, int out_size) {
  const float* feat  = (const float*)d_in[0];
  const float* W1    = (const float*)d_in[1];
  const float* loop1 = (const float*)d_in[2];
  const float* b1    = (const float*)d_in[3];
  const float* W2    = (const float*)d_in[4];
  const float* loop2 = (const float*)d_in[5];
  const float* b2    = (const float*)d_in[6];
  const int*   src   = (const int*)d_in[7];
  const int*   dst   = (const int*)d_in[8];
  const int*   et    = (const int*)d_in[9];
  float* out = (float*)d_out;

  cudaFuncSetAttribute(k_edge1_fused,
                       cudaFuncAttributeMaxDynamicSharedMemorySize, S_FTOT);
  cudaFuncSetAttribute(k_selfloop,
                       cudaFuncAttributeMaxDynamicSharedMemorySize, S_GEMM);

  // 1: prep (convert + zero)   2: hist+prefix   3: scatter
  k_prep<<<(PREP_TOT + 255) / 256, 256>>>(feat, W1, loop1);
  k_histprefix<<<(N_EDGES + 2047) / 2048, 512>>>(et);
  k_scatter<<<(N_EDGES + 2047) / 2048, 512>>>(src, dst, et);

  // 4: fused edge GEMM (profiled slot)
  k_edge1_fused<<<MAXBLK, 256, S_FTOT>>>();

  // 5: self-loop red-add   6: layer2   7: edge2
  k_selfloop<<<(N_NODES + 127) / 128, 256, S_GEMM>>>(b1);
  k_layer2<<<(N_NODES + 63) / 64, 256>>>(W2, loop2, b2, out);
  k_edge2<<<(N_EDGES + 255) / 256, 256>>>(src, dst, et, out);
}

// round 7
// speedup vs baseline: 3.6758x; 1.2218x over previous
#include <cuda_runtime.h>
#include <cuda_bf16.h>
#include <cstdint>

#define N_NODES 50000
#define N_EDGES 600000
#define N_RELS  19
#define D_IN    128
#define D_HID   64
#define D_OUT   2
#define CHUNK   128
#define MAXBLK  ((N_EDGES + CHUNK - 1) / CHUNK + N_RELS)   // 4707
#define SLBLK   ((N_NODES + 127) / 128)                    // 391

// Scratch (device globals — no allocation allowed in kernel_launch)
__device__ float g_h1[(size_t)N_NODES * D_HID];
__device__ float g_T2[(size_t)N_NODES * N_RELS * D_OUT];
__device__ int   g_cnt[N_RELS];
__device__ int   g_off[N_RELS + 1];
__device__ int   g_cblk[N_RELS + 1];
__device__ int   g_fill[N_RELS];
__device__ int   g_done;
__device__ int   g_esrc[N_EDGES];
__device__ int   g_edst[N_EDGES];
// Preconverted bf16 hi/lo operands
__device__ __align__(256) __nv_bfloat16 g_featH[(size_t)N_NODES * D_IN];
__device__ __align__(256) __nv_bfloat16 g_featL[(size_t)N_NODES * D_IN];
// W images in exact smem layout: per rel [hi 64x136][lo 64x136]; rel 19 = loop1.
#define PITCH 136
#define WIMG_HALVES (2 * 64 * PITCH)    // 34816 B per rel
__device__ __align__(256) __nv_bfloat16 g_wimg[20 * WIMG_HALVES];

// ===========================================================================
__device__ __forceinline__ uint32_t smem_u32(const void* p) {
  uint32_t a;
  asm("{ .reg .u64 t; cvta.to.shared.u64 t, %1; cvt.u32.u64 %0, t; }"
      : "=r"(a) : "l"(p));
  return a;
}
#define LDSM_X4(r, addr)                                                    \
  asm volatile("ldmatrix.sync.aligned.m8n8.x4.shared.b16 {%0,%1,%2,%3}, [%4];" \
               : "=r"((r)[0]), "=r"((r)[1]), "=r"((r)[2]), "=r"((r)[3])     \
               : "r"(addr))
#define MMA_BF16(d, a, b0, b1)                                              \
  asm volatile("mma.sync.aligned.m16n8k16.row.col.f32.bf16.bf16.f32 "       \
               "{%0,%1,%2,%3}, {%4,%5,%6,%7}, {%8,%9}, {%0,%1,%2,%3};"      \
               : "+f"((d)[0]), "+f"((d)[1]), "+f"((d)[2]), "+f"((d)[3])     \
               : "r"((a)[0]), "r"((a)[1]), "r"((a)[2]), "r"((a)[3]),        \
                 "r"(b0), "r"(b1))
#define CP16(dst, src)                                                      \
  asm volatile("cp.async.cg.shared.global [%0], [%1], 16;"                  \
               :: "r"(dst), "l"(src) : "memory")
#define CP_COMMIT() asm volatile("cp.async.commit_group;" ::: "memory")
#define CP_WAIT0()  asm volatile("cp.async.wait_group 0;" ::: "memory")

// SMEM layout (bytes); 272B rows — ldmatrix conflict-free.
#define S_AH 0
#define S_AL (128 * PITCH * 2)          // 34816
#define S_BH (S_AL + 128 * PITCH * 2)   // 69632 ; B image hi||lo contiguous
#define S_FTOT (S_BH + WIMG_HALVES * 2) // 104448
#define OPITCH 68

// ---------------------------------------------------------------------------
// Prep: feat -> bf16 hi/lo; W1+loop1 -> padded images; zero g_h1 + counters.
// ---------------------------------------------------------------------------
#define FEAT_F4 (N_NODES * 32)
#define W_F4    (20 * 2048)
#define H1_F4   (N_NODES * D_HID / 4)
#define PREP_TOT (FEAT_F4 + W_F4 + H1_F4)

__global__ void __launch_bounds__(256) k_prep(
    const float* __restrict__ feat, const float* __restrict__ W1,
    const float* __restrict__ loop1) {
  int i = blockIdx.x * 256 + threadIdx.x;
  if (i < 21) {
    if (i < N_RELS) g_cnt[i] = 0;
    if (i == 20) g_done = 0;
  }
  if (i < FEAT_F4) {
    float4 v = *(const float4*)(feat + (size_t)i * 4);
    __nv_bfloat16 h[4], l[4];
    float x[4] = {v.x, v.y, v.z, v.w};
    #pragma unroll
    for (int j = 0; j < 4; j++) {
      h[j] = __float2bfloat16_rn(x[j]);
      l[j] = __float2bfloat16_rn(x[j] - __bfloat162float(h[j]));
    }
    *(uint2*)(g_featH + (size_t)i * 4) = *(uint2*)h;
    *(uint2*)(g_featL + (size_t)i * 4) = *(uint2*)l;
  } else if (i < FEAT_F4 + W_F4) {
    int j = i - FEAT_F4;
    int rel = j >> 11, rem = j & 2047;
    int k = rem >> 4, o4 = rem & 15;
    const float* srcp = (rel < N_RELS) ? (W1 + ((size_t)rel * D_IN + k) * D_HID)
                                       : (loop1 + (size_t)k * D_HID);
    float4 v = *(const float4*)(srcp + o4 * 4);
    float x[4] = {v.x, v.y, v.z, v.w};
    __nv_bfloat16* img = g_wimg + (size_t)rel * WIMG_HALVES;
    #pragma unroll
    for (int jj = 0; jj < 4; jj++) {
      int o = o4 * 4 + jj;
      __nv_bfloat16 h = __float2bfloat16_rn(x[jj]);
      img[o * PITCH + k] = h;
      img[64 * PITCH + o * PITCH + k] =
          __float2bfloat16_rn(x[jj] - __bfloat162float(h));
    }
  } else if (i < PREP_TOT) {
    int j = i - FEAT_F4 - W_F4;
    *(float4*)(g_h1 + (size_t)j * 4) = make_float4(0.f, 0.f, 0.f, 0.f);
  }
}

// ---------------------------------------------------------------------------
// Hist + prefix (done-counter; last block computes offsets).
// ---------------------------------------------------------------------------
__global__ void __launch_bounds__(512) k_histprefix(const int* __restrict__ et) {
  __shared__ int lh[N_RELS];
  if (threadIdx.x < N_RELS) lh[threadIdx.x] = 0;
  __syncthreads();
  int base = blockIdx.x * 2048;
  #pragma unroll
  for (int j = 0; j < 4; j++) {
    int e = base + j * 512 + threadIdx.x;
    if (e < N_EDGES) atomicAdd(&lh[__ldg(et + e)], 1);
  }
  __syncthreads();
  if (threadIdx.x < N_RELS && lh[threadIdx.x])
    atomicAdd(&g_cnt[threadIdx.x], lh[threadIdx.x]);
  __threadfence();
  __syncthreads();
  if (threadIdx.x == 0) {
    int old = atomicAdd(&g_done, 1);
    if (old == (int)gridDim.x - 1) {
      int o = 0, cb = 0;
      for (int r = 0; r < N_RELS; r++) {
        g_off[r] = o; g_cblk[r] = cb; g_fill[r] = o;
        o += g_cnt[r];
        cb += (g_cnt[r] + CHUNK - 1) / CHUNK;
      }
      g_off[N_RELS] = o; g_cblk[N_RELS] = cb;
    }
  }
}

__global__ void __launch_bounds__(512) k_scatter(
    const int* __restrict__ src, const int* __restrict__ dst,
    const int* __restrict__ et) {
  __shared__ int lh[N_RELS], lbase[N_RELS];
  if (threadIdx.x < N_RELS) lh[threadIdx.x] = 0;
  __syncthreads();
  int base = blockIdx.x * 2048;
  int r[4], s[4], d[4], idx[4];
  #pragma unroll
  for (int j = 0; j < 4; j++) {
    int e = base + j * 512 + threadIdx.x;
    r[j] = -1;
    if (e < N_EDGES) {
      r[j] = __ldg(et + e); s[j] = __ldg(src + e); d[j] = __ldg(dst + e);
      idx[j] = atomicAdd(&lh[r[j]], 1);
    }
  }
  __syncthreads();
  if (threadIdx.x < N_RELS)
    lbase[threadIdx.x] = lh[threadIdx.x]
        ? atomicAdd(&g_fill[threadIdx.x], lh[threadIdx.x]) : 0;
  __syncthreads();
  #pragma unroll
  for (int j = 0; j < 4; j++)
    if (r[j] >= 0) {
      int pos = lbase[r[j]] + idx[j];
      g_esrc[pos] = s[j]; g_edst[pos] = d[j];
    }
}

// ---------------------------------------------------------------------------
// Shared MMA core (term loop kept rolled to bound register pressure).
// ---------------------------------------------------------------------------
__device__ __forceinline__ void mma_core(uint32_t sb, int wid, int lane,
                                         float acc[2][4][4]) {
  const int mrow = (wid & 3) * 32, ncol = (wid >> 2) * 32;
  const int lr = lane & 15, lc = lane >> 4;
  const uint32_t aoff0 = ((uint32_t)(mrow + lr) * PITCH + (uint32_t)lc * 8) * 2;
  const uint32_t aoff1 = aoff0 + 16 * PITCH * 2;
  const uint32_t boff0 = ((uint32_t)(ncol + lr) * PITCH + (uint32_t)lc * 8) * 2;
  const uint32_t boff1 = boff0 + 16 * PITCH * 2;
  #pragma unroll
  for (int mi = 0; mi < 2; mi++)
    #pragma unroll
    for (int ni = 0; ni < 4; ni++)
      #pragma unroll
      for (int c = 0; c < 4; c++) acc[mi][ni][c] = 0.f;
  #pragma unroll 1
  for (int term = 0; term < 3; term++) {
    const uint32_t ab = sb + ((term == 1) ? S_AL : S_AH);
    const uint32_t bb = sb + S_BH + ((term == 2) ? 64 * PITCH * 2 : 0);
    #pragma unroll
    for (int k0 = 0; k0 < 8; k0++) {
      const uint32_t ka = (uint32_t)k0 * 32;
      uint32_t A0[4], A1[4], B0[4], B1[4];
      LDSM_X4(A0, ab + aoff0 + ka);
      LDSM_X4(A1, ab + aoff1 + ka);
      LDSM_X4(B0, bb + boff0 + ka);
      LDSM_X4(B1, bb + boff1 + ka);
      MMA_BF16(acc[0][0], A0, B0[0], B0[2]);
      MMA_BF16(acc[0][1], A0, B0[1], B0[3]);
      MMA_BF16(acc[0][2], A0, B1[0], B1[2]);
      MMA_BF16(acc[0][3], A0, B1[1], B1[3]);
      MMA_BF16(acc[1][0], A1, B0[0], B0[2]);
      MMA_BF16(acc[1][1], A1, B0[1], B0[3]);
      MMA_BF16(acc[1][2], A1, B1[0], B1[2]);
      MMA_BF16(acc[1][3], A1, B1[1], B1[3]);
    }
  }
}

// ---------------------------------------------------------------------------
// Fused layer-1: edge chunks (128 edges of one relation) + self-loop tiles.
// 2 CTAs/SM via launch bounds; indices read directly via __ldg (3 barriers).
// ---------------------------------------------------------------------------
__global__ void __launch_bounds__(256, 2) k_edge1_fused(
    const float* __restrict__ b1) {
  extern __shared__ char sm[];
  const uint32_t sb = smem_u32(sm);
  const int tid = threadIdx.x, wid = tid >> 5, lane = tid & 31;

  const int cblkN = __ldg(&g_cblk[N_RELS]);
  const int b = blockIdx.x;
  const bool is_edge = (b < cblkN);
  int r, e0 = 0, m = 0, n0 = 0;
  if (is_edge) {
    r = 0;
    while (b >= __ldg(&g_cblk[r + 1])) r++;
    int off = __ldg(&g_off[r]);
    e0 = off + (b - __ldg(&g_cblk[r])) * CHUNK;
    m = min(CHUNK, off + __ldg(&g_cnt[r]) - e0);
  } else {
    int sl = b - cblkN;
    if (sl >= SLBLK) return;
    r = N_RELS;
    n0 = sl * 128;
  }

  // B image: 2176 x 16B cp.async (hi||lo planes, exact smem layout).
  const char* wsrc = (const char*)(g_wimg + (size_t)r * WIMG_HALVES);
  #pragma unroll
  for (int t = 0; t < 9; t++) {
    int idx = tid + t * 256;
    if (idx < WIMG_HALVES * 2 / 16)
      CP16(sb + S_BH + idx * 16, wsrc + idx * 16);
  }
  // A: 128 rows x (16 hi + 16 lo) 16B chunks; gather or dense.
  #pragma unroll
  for (int t = 0; t < 16; t++) {
    int idx = tid + t * 256;
    int row = idx >> 5, c = idx & 31;
    int s = is_edge ? __ldg(&g_esrc[e0 + min(row, m - 1)])
                    : min(n0 + row, N_NODES - 1);
    int cc = c & 15;
    const char* base = (c < 16) ? (const char*)g_featH : (const char*)g_featL;
    uint32_t doff = ((c < 16) ? S_AH : S_AL) +
                    (uint32_t)row * (PITCH * 2) + (uint32_t)cc * 16;
    CP16(sb + doff, base + (size_t)s * 256 + cc * 16);
  }
  CP_COMMIT();
  CP_WAIT0();
  __syncthreads();

  float acc[2][4][4];
  mma_core(sb, wid, lane, acc);

  const int g = lane >> 2, tq = lane & 3;
  const int mrow = (wid & 3) * 32, ncol = (wid >> 2) * 32;

  if (!is_edge) {
    // Self-loop: red-add (acc + b1) directly into g_h1.
    #pragma unroll
    for (int mi = 0; mi < 2; mi++) {
      int r0 = n0 + mrow + mi * 16 + g;
      #pragma unroll
      for (int ni = 0; ni < 4; ni++) {
        int col = ncol + ni * 8 + tq * 2;
        float bx = __ldg(b1 + col), by = __ldg(b1 + col + 1);
        if (r0 < N_NODES)
          asm volatile("red.global.add.v2.f32 [%0], {%1,%2};"
                       :: "l"(g_h1 + (size_t)r0 * D_HID + col),
                          "f"(acc[mi][ni][0] + bx), "f"(acc[mi][ni][1] + by)
                       : "memory");
        if (r0 + 8 < N_NODES)
          asm volatile("red.global.add.v2.f32 [%0], {%1,%2};"
                       :: "l"(g_h1 + (size_t)(r0 + 8) * D_HID + col),
                          "f"(acc[mi][ni][2] + bx), "f"(acc[mi][ni][3] + by)
                       : "memory");
      }
    }
    return;
  }

  __syncthreads();   // A reads done before aliasing with sout
  float* sout = (float*)sm;
  #pragma unroll
  for (int mi = 0; mi < 2; mi++) {
    int row = mrow + mi * 16 + g;
    #pragma unroll
    for (int ni = 0; ni < 4; ni++) {
      int col = ncol + ni * 8 + tq * 2;
      *(float2*)&sout[row * OPITCH + col] =
          make_float2(acc[mi][ni][0], acc[mi][ni][1]);
      *(float2*)&sout[(row + 8) * OPITCH + col] =
          make_float2(acc[mi][ni][2], acc[mi][ni][3]);
    }
  }
  __syncthreads();

  #pragma unroll
  for (int t = 0; t < 8; t++) {
    int i = (tid + t * 256) >> 4, q = tid & 15;
    if (i < m) {
      int d = __ldg(&g_edst[e0 + i]);
      float4 v = *(const float4*)&sout[i * OPITCH + q * 4];
      float* p = g_h1 + (size_t)d * D_HID + q * 4;
      asm volatile("red.global.add.v4.f32 [%0], {%1,%2,%3,%4};"
                   :: "l"(p), "f"(v.x), "f"(v.y), "f"(v.z), "f"(v.w)
                   : "memory");
    }
  }
}

// ---------------------------------------------------------------------------
// Layer 2 + edge2 (unchanged).
// ---------------------------------------------------------------------------
__global__ void __launch_bounds__(256) k_layer2(
    const float* __restrict__ W2, const float* __restrict__ loop2,
    const float* __restrict__ b2, float* __restrict__ out) {
  __shared__ float sH[64][65];
  __shared__ float sW[N_RELS * D_HID * D_OUT];
  __shared__ float sL[D_HID * D_OUT + D_OUT];
  const int n0 = blockIdx.x * 64;

  for (int i = threadIdx.x; i < N_RELS * D_HID * D_OUT; i += 256) sW[i] = W2[i];
  for (int i = threadIdx.x; i < D_HID * D_OUT; i += 256) sL[i] = loop2[i];
  if (threadIdx.x < D_OUT) sL[D_HID * D_OUT + threadIdx.x] = b2[threadIdx.x];
  for (int i = threadIdx.x; i < 64 * D_HID; i += 256) {
    int n = i >> 6, k = i & 63;
    float v = 0.f;
    if (n0 + n < N_NODES) v = g_h1[(size_t)(n0 + n) * D_HID + k];
    sH[n][k] = fmaxf(v, 0.f);
  }
  __syncthreads();

  const int node = threadIdx.x >> 2;
  const int rg   = threadIdx.x & 3;
  float acc[5][2] = {};
  float s0 = 0.f, s1 = 0.f;
  for (int k = 0; k < D_HID; k++) {
    float f = sH[node][k];
    #pragma unroll
    for (int i = 0; i < 5; i++) {
      int r = rg + 4 * i;
      if (r < N_RELS) {
        acc[i][0] += f * sW[(r * D_HID + k) * 2];
        acc[i][1] += f * sW[(r * D_HID + k) * 2 + 1];
      }
    }
    if (rg == 0) { s0 += f * sL[k * 2]; s1 += f * sL[k * 2 + 1]; }
  }

  int n = n0 + node;
  if (n < N_NODES) {
    #pragma unroll
    for (int i = 0; i < 5; i++) {
      int r = rg + 4 * i;
      if (r < N_RELS)
        *(float2*)&g_T2[((size_t)n * N_RELS + r) * D_OUT] =
            make_float2(acc[i][0], acc[i][1]);
    }
    if (rg == 0)
      *(float2*)&out[(size_t)n * D_OUT] =
          make_float2(s0 + sL[D_HID * D_OUT], s1 + sL[D_HID * D_OUT + 1]);
  }
}

__global__ void __launch_bounds__(256) k_edge2(
    const int* __restrict__ src, const int* __restrict__ dst,
    const int* __restrict__ et, float* __restrict__ out) {
  int e = blockIdx.x * 256 + threadIdx.x;
  if (e >= N_EDGES) return;
  int s = __ldg(src + e), d = __ldg(dst + e), r = __ldg(et + e);
  const float2 v = *(const float2*)(g_T2 + ((size_t)s * N_RELS + r) * D_OUT);
  asm volatile("red.global.add.v2.f32 [%0], {%1,%2};"
               :: "l"(out + (size_t)d * D_OUT), "f"(v.x), "f"(v.y)
               : "memory");
}

// ---------------------------------------------------------------------------
extern "C" void kernel_launch(void* const* d_in, const int* in_sizes, int n_in,
                              void* d_out, int out_size) {
  const float* feat  = (const float*)d_in[0];
  const float* W1    = (const float*)d_in[1];
  const float* loop1 = (const float*)d_in[2];
  const float* b1    = (const float*)d_in[3];
  const float* W2    = (const float*)d_in[4];
  const float* loop2 = (const float*)d_in[5];
  const float* b2    = (const float*)d_in[6];
  const int*   src   = (const int*)d_in[7];
  const int*   dst   = (const int*)d_in[8];
  const int*   et    = (const int*)d_in[9];
  float* out = (float*)d_out;

  cudaFuncSetAttribute(k_edge1_fused,
                       cudaFuncAttributeMaxDynamicSharedMemorySize, S_FTOT);

  // 1: prep   2: hist+prefix   3: scatter
  k_prep<<<(PREP_TOT + 255) / 256, 256>>>(feat, W1, loop1);
  k_histprefix<<<(N_EDGES + 2047) / 2048, 512>>>(et);
  k_scatter<<<(N_EDGES + 2047) / 2048, 512>>>(src, dst, et);

  // 4: fused edge GEMM + self-loop (profiled slot)
  k_edge1_fused<<<MAXBLK + SLBLK, 256, S_FTOT>>>(b1);

  // 5: layer2   6: edge2
  k_layer2<<<(N_NODES + 63) / 64, 256>>>(W2, loop2, b2, out);
  k_edge2<<<(N_EDGES + 255) / 256, 256>>>(src, dst, et, out);
}